// round 5
// baseline (speedup 1.0000x reference)
#include <cuda_runtime.h>
#include <cuda_bf16.h>
#include <cstdint>
#include <math.h>

#define DM 512
#define NH 8
#define HD 64
#define DFF 2048
#define BB 2
#define SS 2048
#define NT (BB*SS)
#define BH (BB*NH)
#define QKVLD 1536

#define SWZ(off) ((off) ^ (((off) >> 3) & 0x70))

__device__ __forceinline__ uint32_t smem_to_u32(const void* smem_ptr) {
    uint32_t addr;
    asm("{ .reg .u64 tmp; cvta.to.shared.u64 tmp, %1; cvt.u32.u64 %0, tmp; }"
        : "=r"(addr) : "l"(smem_ptr));
    return addr;
}

#define LDMATRIX_X4(r, addr) \
    asm volatile("ldmatrix.sync.aligned.m8n8.x4.shared.b16 {%0,%1,%2,%3}, [%4];" \
        : "=r"((r)[0]), "=r"((r)[1]), "=r"((r)[2]), "=r"((r)[3]) : "r"(addr))

#define MMA_BF16(c, a, b0, b1) \
    asm volatile("mma.sync.aligned.m16n8k16.row.col.f32.bf16.bf16.f32 " \
        "{%0,%1,%2,%3}, {%4,%5,%6,%7}, {%8,%9}, {%0,%1,%2,%3};" \
        : "+f"((c)[0]), "+f"((c)[1]), "+f"((c)[2]), "+f"((c)[3]) \
        : "r"((a)[0]), "r"((a)[1]), "r"((a)[2]), "r"((a)[3]), "r"(b0), "r"(b1))

#define CP_ASYNC16(dst, src) \
    asm volatile("cp.async.cg.shared.global [%0], [%1], 16;" :: "r"(dst), "l"(src))
#define CP_COMMIT() asm volatile("cp.async.commit_group;" ::: "memory")
#define CP_WAIT(n)  asm volatile("cp.async.wait_group %0;" :: "n"(n) : "memory")

// ===================== static device scratch =====================
__device__ __nv_bfloat16 g_x_hi[NT * DM],  g_x_lo[NT * DM];
__device__ __nv_bfloat16 g_qkv_hi[NT * QKVLD], g_qkv_lo[NT * QKVLD];
__device__ __nv_bfloat16 g_vt_hi[NT * DM], g_vt_lo[NT * DM];   // [bh][d][s]
__device__ __nv_bfloat16 g_ctx_hi[NT * DM], g_ctx_lo[NT * DM];
__device__ __nv_bfloat16 g_h_hi[NT * DM],  g_h_lo[NT * DM];
__device__ __nv_bfloat16 g_f1_hi[NT * DFF], g_f1_lo[NT * DFF];

__device__ __nv_bfloat16 g_wqkv_hi[QKVLD * DM], g_wqkv_lo[QKVLD * DM];  // [N=1536,K=512]
__device__ __nv_bfloat16 g_wo_hi[DM * DM], g_wo_lo[DM * DM];
__device__ __nv_bfloat16 g_w1_hi[DM * DFF], g_w1_lo[DM * DFF];
__device__ __nv_bfloat16 g_w2_hi[DM * DFF], g_w2_lo[DM * DFF];
__device__ float g_bqkv[QKVLD];

__device__ float g_ao[NT * DM];
__device__ float g_h[NT * DM];
__device__ float g_ff2[NT * DM];

// ===================== helpers =====================
__device__ __forceinline__ void split_bf16(float x, __nv_bfloat16& h, __nv_bfloat16& l) {
    h = __float2bfloat16(x);
    l = __float2bfloat16(x - __bfloat162float(h));
}
__device__ __forceinline__ void pack_split2(float x, float y, uint32_t& hi, uint32_t& lo) {
    __nv_bfloat16 hx, lx, hy, ly;
    split_bf16(x, hx, lx);
    split_bf16(y, hy, ly);
    __nv_bfloat162 H(hx, hy), L(lx, ly);
    hi = *(uint32_t*)&H;
    lo = *(uint32_t*)&L;
}

__global__ void cvt_kernel(const float* __restrict__ in,
                           __nv_bfloat16* __restrict__ hi,
                           __nv_bfloat16* __restrict__ lo, int n)
{
    int i = blockIdx.x * 256 + threadIdx.x;
    if (i < n) { __nv_bfloat16 h, l; split_bf16(in[i], h, l); hi[i] = h; lo[i] = l; }
}

__global__ void concat_bias_kernel(const float* __restrict__ a, const float* __restrict__ b,
                                   const float* __restrict__ c, float* __restrict__ o)
{
    int i = blockIdx.x * 256 + threadIdx.x;  // 0..1535
    float v = (i < 512) ? a[i] : (i < 1024) ? b[i - 512] : c[i - 1024];
    o[i] = v;
}

// W[K,N] fp32 -> WT[N,K] hi/lo bf16
__global__ void wtrans_kernel(const float* __restrict__ W, int K, int N,
                              __nv_bfloat16* __restrict__ Thi,
                              __nv_bfloat16* __restrict__ Tlo)
{
    __shared__ float tile[32][33];
    int n0 = blockIdx.x * 32, k0 = blockIdx.y * 32;
    int tx = threadIdx.x & 31, ty = threadIdx.x >> 5;
    #pragma unroll
    for (int i = 0; i < 32; i += 8)
        tile[ty + i][tx] = W[(size_t)(k0 + ty + i) * N + n0 + tx];
    __syncthreads();
    #pragma unroll
    for (int i = 0; i < 32; i += 8) {
        float v = tile[tx][ty + i];
        __nv_bfloat16 h, l; split_bf16(v, h, l);
        size_t dst = (size_t)(n0 + ty + i) * K + k0 + tx;
        Thi[dst] = h; Tlo[dst] = l;
    }
}

// v planes inside qkv buffer [token, 1024 + h*64 + d] -> vT planes [bh][d][s]
__global__ void vtrans_kernel(const __nv_bfloat16* __restrict__ vh,
                              const __nv_bfloat16* __restrict__ vl,
                              __nv_bfloat16* __restrict__ oth,
                              __nv_bfloat16* __restrict__ otl)
{
    __shared__ unsigned short th[64][65];
    __shared__ unsigned short tl[64][65];
    int bh = blockIdx.y; int b = bh >> 3, h = bh & 7;
    int s0 = blockIdx.x * 64;
    for (int i = threadIdx.x; i < 64 * 64; i += 256) {
        int r = i >> 6, c = i & 63;
        size_t src = (size_t)(b * SS + s0 + r) * QKVLD + 1024 + h * 64 + c;
        th[r][c] = ((const unsigned short*)vh)[src];
        tl[r][c] = ((const unsigned short*)vl)[src];
    }
    __syncthreads();
    for (int i = threadIdx.x; i < 64 * 64; i += 256) {
        int d = i >> 6, s = i & 63;
        size_t dst = ((size_t)bh * 64 + d) * SS + s0 + s;
        ((unsigned short*)oth)[dst] = th[s][d];
        ((unsigned short*)otl)[dst] = tl[s][d];
    }
}

// ===================== pipelined split-bf16 mma.sync GEMM v2 =====================
// BM=128, BN=128, BK=32, double-buffered cp.async.
// smem row layout (128B): [hi k0..31 | lo k0..31], A tile 16KB, B tile 16KB per buffer.
// EPI: 1 +bias, 2 +bias+relu
template<int EPI, bool OUT_PLANES>
__global__ __launch_bounds__(256) void gemm128_kernel(
    const __nv_bfloat16* __restrict__ Ahi, const __nv_bfloat16* __restrict__ Alo,
    long lda,
    const __nv_bfloat16* __restrict__ Bhi, const __nv_bfloat16* __restrict__ Blo,
    long ldb,
    const float* __restrict__ bias,
    float* __restrict__ Cf,
    __nv_bfloat16* __restrict__ Chi, __nv_bfloat16* __restrict__ Clo,
    long ldc,
    int K)
{
    extern __shared__ __align__(16) char sm[];
    const uint32_t smb = smem_to_u32(sm);

    const int tid = threadIdx.x;
    const int lane = tid & 31;
    const int wid = tid >> 5;
    const int wr = wid >> 1;          // 0..3
    const int wc = wid & 1;           // 0..1
    const int m0 = wr * 32;
    const int n0 = wc * 64;

    const int row0 = blockIdx.y * 128;
    const int col0 = blockIdx.x * 128;

    float acc[2][8][4] = {};

    const int aRow = m0 + (lane & 15);
    const int aOff = (lane >> 4) << 4;
    const int bRow = (lane & 7) + ((lane >> 4) & 1) * 8;
    const int bOff = ((lane >> 3) & 1) << 4;

    auto load_chunk = [&](int chunk, int buf) {
        const int c0 = chunk << 5;
        const uint32_t base = smb + buf * 32768;
        #pragma unroll
        for (int t = 0; t < 8; t++) {
            int i = tid + t * 256;        // 0..2047
            int isB = i >> 10;
            int j = i & 1023;
            int r = j >> 3;               // 0..127
            int g = j & 7;
            int plane = g >> 2;           // 0 hi, 1 lo
            int seg = g & 3;
            const __nv_bfloat16* src;
            if (isB) src = (plane ? Blo : Bhi) + (size_t)(col0 + r) * ldb + c0 + seg * 8;
            else     src = (plane ? Alo : Ahi) + (size_t)(row0 + r) * lda + c0 + seg * 8;
            uint32_t dst = base + isB * 16384 + SWZ((uint32_t)(r * 128 + plane * 64 + seg * 16));
            CP_ASYNC16(dst, src);
        }
        CP_COMMIT();
    };

    const int nchunks = K >> 5;
    load_chunk(0, 0);

    for (int chunk = 0; chunk < nchunks; chunk++) {
        const int buf = chunk & 1;
        if (chunk + 1 < nchunks) { load_chunk(chunk + 1, buf ^ 1); CP_WAIT(1); }
        else                      { CP_WAIT(0); }
        __syncthreads();

        const uint32_t abase = smb + buf * 32768;
        const uint32_t bbase = abase + 16384;

        #pragma unroll
        for (int ks = 0; ks < 2; ks++) {
            const int kb = ks * 32;
            uint32_t a_hi[2][4], a_lo[2][4], b_hi[4][4], b_lo[4][4];
            #pragma unroll
            for (int mt = 0; mt < 2; mt++) {
                uint32_t roff = (uint32_t)((aRow + mt * 16) * 128);
                LDMATRIX_X4(a_hi[mt], abase + SWZ(roff + kb + aOff));
                LDMATRIX_X4(a_lo[mt], abase + SWZ(roff + 64 + kb + aOff));
            }
            #pragma unroll
            for (int np = 0; np < 4; np++) {
                uint32_t roff = (uint32_t)((n0 + np * 16 + bRow) * 128);
                LDMATRIX_X4(b_hi[np], bbase + SWZ(roff + kb + bOff));
                LDMATRIX_X4(b_lo[np], bbase + SWZ(roff + 64 + kb + bOff));
            }
            #pragma unroll
            for (int mt = 0; mt < 2; mt++)
                #pragma unroll
                for (int nt = 0; nt < 8; nt++) {
                    const int np = nt >> 1, hb = (nt & 1) * 2;
                    MMA_BF16(acc[mt][nt], a_hi[mt], b_hi[np][hb], b_hi[np][hb + 1]);
                    MMA_BF16(acc[mt][nt], a_hi[mt], b_lo[np][hb], b_lo[np][hb + 1]);
                    MMA_BF16(acc[mt][nt], a_lo[mt], b_hi[np][hb], b_hi[np][hb + 1]);
                }
        }
        __syncthreads();
    }

    // ---- epilogue ----
    #pragma unroll
    for (int mt = 0; mt < 2; mt++)
        #pragma unroll
        for (int nt = 0; nt < 8; nt++) {
            const long rbase = row0 + m0 + mt * 16 + (lane >> 2);
            const long col = col0 + n0 + nt * 8 + (lane & 3) * 2;
            float b0f = bias[col], b1f = bias[col + 1];
            #pragma unroll
            for (int half = 0; half < 2; half++) {
                const long r = rbase + half * 8;
                float v0 = acc[mt][nt][half * 2 + 0] + b0f;
                float v1 = acc[mt][nt][half * 2 + 1] + b1f;
                if (EPI == 2) { v0 = fmaxf(v0, 0.f); v1 = fmaxf(v1, 0.f); }
                const size_t dst = (size_t)(r * ldc + col);
                if (Cf) *(float2*)(Cf + dst) = make_float2(v0, v1);
                if (OUT_PLANES) {
                    uint32_t hi, lo;
                    pack_split2(v0, v1, hi, lo);
                    *(uint32_t*)(Chi + dst) = hi;
                    *(uint32_t*)(Clo + dst) = lo;
                }
            }
        }
}

// ===================== fused flash attention =====================
__global__ __launch_bounds__(256) void flash_attn_kernel(
    const __nv_bfloat16* __restrict__ qkvh, const __nv_bfloat16* __restrict__ qkvl,
    const __nv_bfloat16* __restrict__ vth_, const __nv_bfloat16* __restrict__ vtl_,
    __nv_bfloat16* __restrict__ ch_, __nv_bfloat16* __restrict__ cl_)
{
    extern __shared__ __align__(16) char sm[];
    const uint32_t smb = smem_to_u32(sm);
    const int tid = threadIdx.x, lane = tid & 31, wid = tid >> 5;
    const int bh = blockIdx.y;
    const int b = bh >> 3, h = bh & 7;
    const int q0 = blockIdx.x * 128;

    const __nv_bfloat16* qhp = qkvh + (size_t)(b * SS + q0) * QKVLD + h * 64;
    const __nv_bfloat16* qlp = qkvl + (size_t)(b * SS + q0) * QKVLD + h * 64;
    const __nv_bfloat16* khp = qkvh + (size_t)b * SS * QKVLD + 512 + h * 64;
    const __nv_bfloat16* klp = qkvl + (size_t)b * SS * QKVLD + 512 + h * 64;
    const __nv_bfloat16* vthp = vth_ + (size_t)bh * 64 * SS;
    const __nv_bfloat16* vtlp = vtl_ + (size_t)bh * 64 * SS;

    // ---- stage Q, grab fragments ----
    #pragma unroll
    for (int t = 0; t < 4; t++) {
        int i = tid + t * 256;
        int r = i >> 3, seg = i & 7;
        uint32_t off = SWZ((uint32_t)(r * 128 + seg * 16));
        *(float4*)(sm + off)         = *(const float4*)(qhp + (size_t)r * QKVLD + seg * 8);
        *(float4*)(sm + 16384 + off) = *(const float4*)(qlp + (size_t)r * QKVLD + seg * 8);
    }
    __syncthreads();
    uint32_t qfh[4][4], qfl[4][4];
    {
        const int aRow = wid * 16 + (lane & 15);
        const int aCol = (lane >> 4) << 4;
        #pragma unroll
        for (int ks = 0; ks < 4; ks++) {
            uint32_t off = SWZ((uint32_t)(aRow * 128 + ks * 32 + aCol));
            LDMATRIX_X4(qfh[ks], smb + off);
            LDMATRIX_X4(qfl[ks], smb + 16384 + off);
        }
    }
    __syncthreads();

    const int bRow = (lane & 7) + ((lane >> 4) & 1) * 8;
    const int bCol = ((lane >> 3) & 1) << 4;

    float acc_o[8][4] = {};
    float m0r = -1e30f, m1r = -1e30f, l0 = 0.f, l1 = 0.f;

    auto load_tile = [&](int it, int buf) {
        const int kv0 = it * 64;
        const uint32_t base = smb + buf * 32768;
        #pragma unroll
        for (int t = 0; t < 8; t++) {
            int i = tid + t * 256;
            int plane = i >> 9;
            int r = (i >> 3) & 63;
            int seg = i & 7;
            uint32_t dst = base + plane * 8192 + SWZ((uint32_t)(r * 128 + seg * 16));
            const __nv_bfloat16* src;
            if (plane == 0)      src = khp  + (size_t)(kv0 + r) * QKVLD + seg * 8;
            else if (plane == 1) src = klp  + (size_t)(kv0 + r) * QKVLD + seg * 8;
            else if (plane == 2) src = vthp + (size_t)r * SS + kv0 + seg * 8;
            else                 src = vtlp + (size_t)r * SS + kv0 + seg * 8;
            CP_ASYNC16(dst, src);
        }
        CP_COMMIT();
    };

    load_tile(0, 0);

    const int NIT = SS / 64;
    for (int it = 0; it < NIT; it++) {
        const int buf = it & 1;
        if (it + 1 < NIT) { load_tile(it + 1, buf ^ 1); CP_WAIT(1); }
        else               { CP_WAIT(0); }
        __syncthreads();

        const uint32_t kbase = smb + buf * 32768;
        const uint32_t vbase = kbase + 16384;

        float s[8][4] = {};
        #pragma unroll
        for (int ks = 0; ks < 4; ks++) {
            uint32_t bhf[4][4], blf[4][4];
            #pragma unroll
            for (int np = 0; np < 4; np++) {
                uint32_t off = SWZ((uint32_t)((np * 16 + bRow) * 128 + ks * 32 + bCol));
                LDMATRIX_X4(bhf[np], kbase + off);
                LDMATRIX_X4(blf[np], kbase + 8192 + off);
            }
            #pragma unroll
            for (int nt = 0; nt < 8; nt++) {
                const int np = nt >> 1, hb = (nt & 1) * 2;
                MMA_BF16(s[nt], qfh[ks], bhf[np][hb], bhf[np][hb + 1]);
                MMA_BF16(s[nt], qfh[ks], blf[np][hb], blf[np][hb + 1]);
                MMA_BF16(s[nt], qfl[ks], bhf[np][hb], bhf[np][hb + 1]);
            }
        }

        float mx0 = -1e30f, mx1 = -1e30f;
        #pragma unroll
        for (int t = 0; t < 8; t++) {
            mx0 = fmaxf(mx0, fmaxf(s[t][0], s[t][1]));
            mx1 = fmaxf(mx1, fmaxf(s[t][2], s[t][3]));
        }
        mx0 = fmaxf(mx0, __shfl_xor_sync(0xffffffffu, mx0, 1));
        mx0 = fmaxf(mx0, __shfl_xor_sync(0xffffffffu, mx0, 2));
        mx1 = fmaxf(mx1, __shfl_xor_sync(0xffffffffu, mx1, 1));
        mx1 = fmaxf(mx1, __shfl_xor_sync(0xffffffffu, mx1, 2));

        const float mn0 = fmaxf(m0r, 0.125f * mx0);
        const float mn1 = fmaxf(m1r, 0.125f * mx1);
        const float alpha0 = __expf(m0r - mn0);
        const float alpha1 = __expf(m1r - mn1);
        m0r = mn0; m1r = mn1;

        float sum0 = 0.f, sum1 = 0.f;
        #pragma unroll
        for (int t = 0; t < 8; t++) {
            float p0 = __expf(fmaf(0.125f, s[t][0], -mn0));
            float p1 = __expf(fmaf(0.125f, s[t][1], -mn0));
            float p2 = __expf(fmaf(0.125f, s[t][2], -mn1));
            float p3 = __expf(fmaf(0.125f, s[t][3], -mn1));
            sum0 += p0 + p1; sum1 += p2 + p3;
            s[t][0] = p0; s[t][1] = p1; s[t][2] = p2; s[t][3] = p3;
        }
        sum0 += __shfl_xor_sync(0xffffffffu, sum0, 1);
        sum0 += __shfl_xor_sync(0xffffffffu, sum0, 2);
        sum1 += __shfl_xor_sync(0xffffffffu, sum1, 1);
        sum1 += __shfl_xor_sync(0xffffffffu, sum1, 2);
        l0 = l0 * alpha0 + sum0;
        l1 = l1 * alpha1 + sum1;
        #pragma unroll
        for (int t = 0; t < 8; t++) {
            acc_o[t][0] *= alpha0; acc_o[t][1] *= alpha0;
            acc_o[t][2] *= alpha1; acc_o[t][3] *= alpha1;
        }

        #pragma unroll
        for (int j = 0; j < 4; j++) {
            uint32_t pa_h[4], pa_l[4];
            pack_split2(s[2*j][0],   s[2*j][1],   pa_h[0], pa_l[0]);
            pack_split2(s[2*j][2],   s[2*j][3],   pa_h[1], pa_l[1]);
            pack_split2(s[2*j+1][0], s[2*j+1][1], pa_h[2], pa_l[2]);
            pack_split2(s[2*j+1][2], s[2*j+1][3], pa_h[3], pa_l[3]);

            uint32_t vhf[4][4], vlf[4][4];
            #pragma unroll
            for (int np = 0; np < 4; np++) {
                uint32_t off = SWZ((uint32_t)((np * 16 + bRow) * 128 + j * 32 + bCol));
                LDMATRIX_X4(vhf[np], vbase + off);
                LDMATRIX_X4(vlf[np], vbase + 8192 + off);
            }
            #pragma unroll
            for (int nt = 0; nt < 8; nt++) {
                const int np = nt >> 1, hb = (nt & 1) * 2;
                MMA_BF16(acc_o[nt], pa_h, vhf[np][hb], vhf[np][hb + 1]);
                MMA_BF16(acc_o[nt], pa_h, vlf[np][hb], vlf[np][hb + 1]);
                MMA_BF16(acc_o[nt], pa_l, vhf[np][hb], vhf[np][hb + 1]);
            }
        }
        __syncthreads();
    }

    const float inv0 = 1.0f / l0;
    const float inv1 = 1.0f / l1;
    const size_t tok0 = (size_t)(b * SS + q0 + wid * 16 + (lane >> 2)) * DM + h * 64;
    #pragma unroll
    for (int t = 0; t < 8; t++) {
        const int dcol = t * 8 + (lane & 3) * 2;
        uint32_t hi, lo;
        pack_split2(acc_o[t][0] * inv0, acc_o[t][1] * inv0, hi, lo);
        *(uint32_t*)(ch_ + tok0 + dcol) = hi;
        *(uint32_t*)(cl_ + tok0 + dcol) = lo;
        pack_split2(acc_o[t][2] * inv1, acc_o[t][3] * inv1, hi, lo);
        *(uint32_t*)(ch_ + tok0 + 8 * DM + dcol) = hi;
        *(uint32_t*)(cl_ + tok0 + 8 * DM + dcol) = lo;
    }
}

// ===================== add + LayerNorm =====================
template<bool PLANES>
__global__ void add_ln_kernel(const float* __restrict__ xa, const float* __restrict__ xb,
                              const float* __restrict__ g, const float* __restrict__ be,
                              float* __restrict__ out,
                              __nv_bfloat16* __restrict__ ohi, __nv_bfloat16* __restrict__ olo)
{
    __shared__ float red[256];
    const int row = blockIdx.x;
    const int t = threadIdx.x;
    const float* pa = xa + (size_t)row * DM;
    const float* pb = xb + (size_t)row * DM;

    float v0 = pa[t] + pb[t];
    float v1 = pa[t + 256] + pb[t + 256];

    red[t] = v0 + v1; __syncthreads();
    for (int s = 128; s > 0; s >>= 1) {
        if (t < s) red[t] += red[t + s];
        __syncthreads();
    }
    float mu = red[0] * (1.0f / DM); __syncthreads();

    float d0 = v0 - mu, d1 = v1 - mu;
    red[t] = d0 * d0 + d1 * d1; __syncthreads();
    for (int s = 128; s > 0; s >>= 1) {
        if (t < s) red[t] += red[t + s];
        __syncthreads();
    }
    float r = rsqrtf(red[0] * (1.0f / DM) + 1e-5f);

    float o0 = d0 * r * g[t] + be[t];
    float o1 = d1 * r * g[t + 256] + be[t + 256];
    out[(size_t)row * DM + t] = o0;
    out[(size_t)row * DM + t + 256] = o1;
    if (PLANES) {
        __nv_bfloat16 h, l;
        split_bf16(o0, h, l); ohi[(size_t)row * DM + t] = h;       olo[(size_t)row * DM + t] = l;
        split_bf16(o1, h, l); ohi[(size_t)row * DM + t + 256] = h; olo[(size_t)row * DM + t + 256] = l;
    }
}

// ===================== launch =====================
extern "C" void kernel_launch(void* const* d_in, const int* in_sizes, int n_in,
                              void* d_out, int out_size)
{
    const float* x   = (const float*)d_in[0];
    const float* Wq  = (const float*)d_in[1];
    const float* bq  = (const float*)d_in[2];
    const float* Wk  = (const float*)d_in[3];
    const float* bk  = (const float*)d_in[4];
    const float* Wv  = (const float*)d_in[5];
    const float* bv  = (const float*)d_in[6];
    const float* Wo  = (const float*)d_in[7];
    const float* bo  = (const float*)d_in[8];
    const float* W1  = (const float*)d_in[9];
    const float* b1  = (const float*)d_in[10];
    const float* W2  = (const float*)d_in[11];
    const float* b2  = (const float*)d_in[12];
    const float* g1  = (const float*)d_in[13];
    const float* be1 = (const float*)d_in[14];
    const float* g2  = (const float*)d_in[15];
    const float* be2 = (const float*)d_in[16];

    #define SYM(p, s) cudaGetSymbolAddress((void**)&p, s)
    float *ao, *hbuf, *ff2, *bqkv;
    __nv_bfloat16 *xh,*xl,*qkh,*qkl,*vth,*vtl,*ch,*cl,*hh,*hl,*f1h,*f1l;
    __nv_bfloat16 *wqkvh,*wqkvl,*woh,*wol,*w1h,*w1l,*w2h,*w2l;
    SYM(ao, g_ao); SYM(hbuf, g_h); SYM(ff2, g_ff2); SYM(bqkv, g_bqkv);
    SYM(xh, g_x_hi); SYM(xl, g_x_lo);
    SYM(qkh, g_qkv_hi); SYM(qkl, g_qkv_lo);
    SYM(vth, g_vt_hi); SYM(vtl, g_vt_lo);
    SYM(ch, g_ctx_hi); SYM(cl, g_ctx_lo);
    SYM(hh, g_h_hi); SYM(hl, g_h_lo);
    SYM(f1h, g_f1_hi); SYM(f1l, g_f1_lo);
    SYM(wqkvh, g_wqkv_hi); SYM(wqkvl, g_wqkv_lo);
    SYM(woh, g_wo_hi); SYM(wol, g_wo_lo);
    SYM(w1h, g_w1_hi); SYM(w1l, g_w1_lo);
    SYM(w2h, g_w2_hi); SYM(w2l, g_w2_lo);
    #undef SYM

    cudaFuncSetAttribute(flash_attn_kernel,
                         cudaFuncAttributeMaxDynamicSharedMemorySize, 65536);
    cudaFuncSetAttribute(gemm128_kernel<1, true>,
                         cudaFuncAttributeMaxDynamicSharedMemorySize, 65536);
    cudaFuncSetAttribute(gemm128_kernel<1, false>,
                         cudaFuncAttributeMaxDynamicSharedMemorySize, 65536);
    cudaFuncSetAttribute(gemm128_kernel<2, true>,
                         cudaFuncAttributeMaxDynamicSharedMemorySize, 65536);

    // 1. convert activations + weights (QKV weights into combined [1536,512] buffer)
    cvt_kernel<<<(NT * DM + 255) / 256, 256>>>(x, xh, xl, NT * DM);
    concat_bias_kernel<<<QKVLD / 256, 256>>>(bq, bk, bv, bqkv);
    wtrans_kernel<<<dim3(DM / 32, DM / 32), 256>>>(Wq, DM, DM, wqkvh, wqkvl);
    wtrans_kernel<<<dim3(DM / 32, DM / 32), 256>>>(Wk, DM, DM, wqkvh + 512 * DM, wqkvl + 512 * DM);
    wtrans_kernel<<<dim3(DM / 32, DM / 32), 256>>>(Wv, DM, DM, wqkvh + 1024 * DM, wqkvl + 1024 * DM);
    wtrans_kernel<<<dim3(DM / 32, DM / 32), 256>>>(Wo, DM, DM, woh, wol);
    wtrans_kernel<<<dim3(DFF / 32, DM / 32), 256>>>(W1, DM, DFF, w1h, w1l);
    wtrans_kernel<<<dim3(DM / 32, DFF / 32), 256>>>(W2, DFF, DM, w2h, w2l);

    // 2. fused QKV projection: [4096,512] @ [512,1536]
    gemm128_kernel<1, true><<<dim3(QKVLD / 128, NT / 128), 256, 65536>>>(
        xh, xl, DM, wqkvh, wqkvl, DM, bqkv, nullptr, qkh, qkl, QKVLD, DM);

    // 3. transpose V per head
    vtrans_kernel<<<dim3(SS / 64, BH), 256>>>(qkh, qkl, vth, vtl);

    // 4. fused flash attention -> ctx planes
    flash_attn_kernel<<<dim3(SS / 128, BH), 256, 65536>>>(
        qkh, qkl, vth, vtl, ch, cl);

    // 5. attn_out = ctx @ Wo + bo (fp32)
    gemm128_kernel<1, false><<<dim3(DM / 128, NT / 128), 256, 65536>>>(
        ch, cl, DM, woh, wol, DM, bo, ao, nullptr, nullptr, DM, DM);

    // 6. h = LN(x + ao)
    add_ln_kernel<true><<<NT, 256>>>(x, ao, g1, be1, hbuf, hh, hl);

    // 7. ff1 = relu(h @ W1 + b1)
    gemm128_kernel<2, true><<<dim3(DFF / 128, NT / 128), 256, 65536>>>(
        hh, hl, DM, w1h, w1l, DM, b1, nullptr, f1h, f1l, DFF, DM);

    // 8. ff2 = ff1 @ W2 + b2 (fp32)
    gemm128_kernel<1, false><<<dim3(DM / 128, NT / 128), 256, 65536>>>(
        f1h, f1l, DFF, w2h, w2l, DFF, b2, ff2, nullptr, nullptr, DM, DFF);

    // 9. out = LN(h + ff2)
    add_ln_kernel<false><<<NT, 256>>>(hbuf, ff2, g2, be2, (float*)d_out, nullptr, nullptr);
}

// round 6
// speedup vs baseline: 1.0632x; 1.0632x over previous
#include <cuda_runtime.h>
#include <cuda_bf16.h>
#include <cstdint>
#include <math.h>

#define DM 512
#define NH 8
#define HD 64
#define DFF 2048
#define BB 2
#define SS 2048
#define NT (BB*SS)
#define BH (BB*NH)
#define QKVLD 1536

#define SWZ(off) ((off) ^ (((off) >> 3) & 0x70))

__device__ __forceinline__ uint32_t smem_to_u32(const void* smem_ptr) {
    uint32_t addr;
    asm("{ .reg .u64 tmp; cvta.to.shared.u64 tmp, %1; cvt.u32.u64 %0, tmp; }"
        : "=r"(addr) : "l"(smem_ptr));
    return addr;
}

#define LDMATRIX_X4(r, addr) \
    asm volatile("ldmatrix.sync.aligned.m8n8.x4.shared.b16 {%0,%1,%2,%3}, [%4];" \
        : "=r"((r)[0]), "=r"((r)[1]), "=r"((r)[2]), "=r"((r)[3]) : "r"(addr))

#define MMA_BF16(c, a, b0, b1) \
    asm volatile("mma.sync.aligned.m16n8k16.row.col.f32.bf16.bf16.f32 " \
        "{%0,%1,%2,%3}, {%4,%5,%6,%7}, {%8,%9}, {%0,%1,%2,%3};" \
        : "+f"((c)[0]), "+f"((c)[1]), "+f"((c)[2]), "+f"((c)[3]) \
        : "r"((a)[0]), "r"((a)[1]), "r"((a)[2]), "r"((a)[3]), "r"(b0), "r"(b1))

#define CP_ASYNC16(dst, src) \
    asm volatile("cp.async.cg.shared.global [%0], [%1], 16;" :: "r"(dst), "l"(src))
#define CP_COMMIT() asm volatile("cp.async.commit_group;" ::: "memory")
#define CP_WAIT(n)  asm volatile("cp.async.wait_group %0;" :: "n"(n) : "memory")

// ===================== static device scratch =====================
__device__ __nv_bfloat16 g_x_hi[NT * DM],  g_x_lo[NT * DM];
__device__ __nv_bfloat16 g_qkv_hi[NT * QKVLD], g_qkv_lo[NT * QKVLD];
__device__ __nv_bfloat16 g_vt_hi[NT * DM], g_vt_lo[NT * DM];   // [bh][d][s]
__device__ __nv_bfloat16 g_ctx_hi[NT * DM], g_ctx_lo[NT * DM];
__device__ __nv_bfloat16 g_h_hi[NT * DM],  g_h_lo[NT * DM];
__device__ __nv_bfloat16 g_f1_hi[NT * DFF], g_f1_lo[NT * DFF];

__device__ __nv_bfloat16 g_wqkv_hi[QKVLD * DM], g_wqkv_lo[QKVLD * DM];  // [N=1536,K=512]
__device__ __nv_bfloat16 g_wo_hi[DM * DM], g_wo_lo[DM * DM];
__device__ __nv_bfloat16 g_w1_hi[DM * DFF], g_w1_lo[DM * DFF];
__device__ __nv_bfloat16 g_w2_hi[DM * DFF], g_w2_lo[DM * DFF];
__device__ float g_bqkv[QKVLD];

__device__ float g_ao[NT * DM];
__device__ float g_h[NT * DM];
__device__ float g_ff2[NT * DM];

// ===================== helpers =====================
__device__ __forceinline__ void split_bf16(float x, __nv_bfloat16& h, __nv_bfloat16& l) {
    h = __float2bfloat16(x);
    l = __float2bfloat16(x - __bfloat162float(h));
}
__device__ __forceinline__ void pack_split2(float x, float y, uint32_t& hi, uint32_t& lo) {
    __nv_bfloat16 hx, lx, hy, ly;
    split_bf16(x, hx, lx);
    split_bf16(y, hy, ly);
    __nv_bfloat162 H(hx, hy), L(lx, ly);
    hi = *(uint32_t*)&H;
    lo = *(uint32_t*)&L;
}

__global__ void cvt_kernel(const float* __restrict__ in,
                           __nv_bfloat16* __restrict__ hi,
                           __nv_bfloat16* __restrict__ lo, int n)
{
    int i = blockIdx.x * 256 + threadIdx.x;
    if (i < n) { __nv_bfloat16 h, l; split_bf16(in[i], h, l); hi[i] = h; lo[i] = l; }
}

__global__ void concat_bias_kernel(const float* __restrict__ a, const float* __restrict__ b,
                                   const float* __restrict__ c, float* __restrict__ o)
{
    int i = blockIdx.x * 256 + threadIdx.x;  // 0..1535
    float v = (i < 512) ? a[i] : (i < 1024) ? b[i - 512] : c[i - 1024];
    o[i] = v;
}

// shared tile body: W[K,N] fp32 -> WT[N,K] hi/lo bf16, one 32x32 tile
__device__ __forceinline__ void wtrans_tile(const float* __restrict__ W, int K, int N,
                                            __nv_bfloat16* __restrict__ Thi,
                                            __nv_bfloat16* __restrict__ Tlo,
                                            int n0, int k0)
{
    __shared__ float tile[32][33];
    int tx = threadIdx.x & 31, ty = threadIdx.x >> 5;
    #pragma unroll
    for (int i = 0; i < 32; i += 8)
        tile[ty + i][tx] = W[(size_t)(k0 + ty + i) * N + n0 + tx];
    __syncthreads();
    #pragma unroll
    for (int i = 0; i < 32; i += 8) {
        float v = tile[tx][ty + i];
        __nv_bfloat16 h, l; split_bf16(v, h, l);
        size_t dst = (size_t)(n0 + ty + i) * K + k0 + tx;
        Thi[dst] = h; Tlo[dst] = l;
    }
}

__global__ void wtrans_kernel(const float* __restrict__ W, int K, int N,
                              __nv_bfloat16* __restrict__ Thi,
                              __nv_bfloat16* __restrict__ Tlo)
{
    wtrans_tile(W, K, N, Thi, Tlo, blockIdx.x * 32, blockIdx.y * 32);
}

// combined Wo + W1 + W2 transpose (1 launch instead of 3)
// Wo: 512x512 -> 256 tiles; W1: K=512,N=2048 -> 1024 tiles; W2: K=2048,N=512 -> 1024 tiles
__global__ void wtrans3_kernel(const float* __restrict__ Wo,
                               __nv_bfloat16* __restrict__ Woh, __nv_bfloat16* __restrict__ Wol,
                               const float* __restrict__ W1,
                               __nv_bfloat16* __restrict__ W1h, __nv_bfloat16* __restrict__ W1l,
                               const float* __restrict__ W2,
                               __nv_bfloat16* __restrict__ W2h, __nv_bfloat16* __restrict__ W2l)
{
    int b = blockIdx.x;
    if (b < 256) {
        // Wo: 16 x 16 tiles (n-major)
        int nt = b & 15, kt = b >> 4;
        wtrans_tile(Wo, DM, DM, Woh, Wol, nt * 32, kt * 32);
    } else if (b < 256 + 1024) {
        int j = b - 256;            // W1: N=2048 (64 ntiles), K=512 (16 ktiles)
        int nt = j & 63, kt = j >> 6;
        wtrans_tile(W1, DM, DFF, W1h, W1l, nt * 32, kt * 32);
    } else {
        int j = b - 1280;           // W2: N=512 (16 ntiles), K=2048 (64 ktiles)
        int nt = j & 15, kt = j >> 4;
        wtrans_tile(W2, DFF, DM, W2h, W2l, nt * 32, kt * 32);
    }
}

// v planes inside qkv buffer [token, 1024 + h*64 + d] -> vT planes [bh][d][s]
__global__ void vtrans_kernel(const __nv_bfloat16* __restrict__ vh,
                              const __nv_bfloat16* __restrict__ vl,
                              __nv_bfloat16* __restrict__ oth,
                              __nv_bfloat16* __restrict__ otl)
{
    __shared__ unsigned short th[64][65];
    __shared__ unsigned short tl[64][65];
    int bh = blockIdx.y; int b = bh >> 3, h = bh & 7;
    int s0 = blockIdx.x * 64;
    for (int i = threadIdx.x; i < 64 * 64; i += 256) {
        int r = i >> 6, c = i & 63;
        size_t src = (size_t)(b * SS + s0 + r) * QKVLD + 1024 + h * 64 + c;
        th[r][c] = ((const unsigned short*)vh)[src];
        tl[r][c] = ((const unsigned short*)vl)[src];
    }
    __syncthreads();
    for (int i = threadIdx.x; i < 64 * 64; i += 256) {
        int d = i >> 6, s = i & 63;
        size_t dst = ((size_t)bh * 64 + d) * SS + s0 + s;
        ((unsigned short*)oth)[dst] = th[s][d];
        ((unsigned short*)otl)[dst] = tl[s][d];
    }
}

// ===================== split-bf16 mma.sync GEMM (R4 proven engine) =====================
// BM=128, BN=64, BK=64, static 48KB smem (4 blocks/SM), LDG->STS staging.
// EPI: 1 +bias, 2 +bias+relu
template<int EPI, bool OUT_PLANES>
__global__ __launch_bounds__(256) void mma_gemm_kernel(
    const __nv_bfloat16* __restrict__ Ahi, const __nv_bfloat16* __restrict__ Alo,
    long lda,
    const __nv_bfloat16* __restrict__ Bhi, const __nv_bfloat16* __restrict__ Blo,
    long ldb,
    const float* __restrict__ bias,
    float* __restrict__ Cf,
    __nv_bfloat16* __restrict__ Chi, __nv_bfloat16* __restrict__ Clo,
    long ldc,
    int K)
{
    __shared__ __align__(16) char sm[49152];
    const uint32_t smb = smem_to_u32(sm);

    const int tid = threadIdx.x;
    const int lane = tid & 31;
    const int wid = tid >> 5;
    const int wr = wid >> 1;
    const int wc = wid & 1;
    const int m0 = wr * 32;
    const int n0w = wc * 32;

    const int row0 = blockIdx.y * 128;
    const int col0 = blockIdx.x * 64;

    float acc[2][4][4] = {};

    const int aRow = m0 + (lane & 15);
    const int aColOff = (lane >> 4) << 4;
    const int bRow0 = n0w + (lane & 7) + ((lane >> 4) & 1) * 8;
    const int bColOff = ((lane >> 3) & 1) << 4;

    const int nchunks = K >> 6;
    for (int chunk = 0; chunk < nchunks; chunk++) {
        const int c0k = chunk << 6;
        #pragma unroll
        for (int t = 0; t < 4; t++) {
            int i = tid + t * 256;
            int r = i >> 3, seg = i & 7;
            size_t src = (size_t)(row0 + r) * lda + c0k + seg * 8;
            uint32_t off = SWZ((uint32_t)(r * 128 + seg * 16));
            *(float4*)(sm + off)         = *(const float4*)(Ahi + src);
            *(float4*)(sm + 16384 + off) = *(const float4*)(Alo + src);
        }
        #pragma unroll
        for (int t = 0; t < 2; t++) {
            int i = tid + t * 256;
            int r = i >> 3, seg = i & 7;
            size_t src = (size_t)(col0 + r) * ldb + c0k + seg * 8;
            uint32_t off = SWZ((uint32_t)(r * 128 + seg * 16));
            *(float4*)(sm + 32768 + off) = *(const float4*)(Bhi + src);
            *(float4*)(sm + 40960 + off) = *(const float4*)(Blo + src);
        }
        __syncthreads();

        #pragma unroll
        for (int ks = 0; ks < 4; ks++) {
            const int kb = ks * 32;
            uint32_t a_hi[2][4], a_lo[2][4], b_hi[2][4], b_lo[2][4];
            #pragma unroll
            for (int mt = 0; mt < 2; mt++) {
                uint32_t off = SWZ((uint32_t)((aRow + mt * 16) * 128 + kb + aColOff));
                LDMATRIX_X4(a_hi[mt], smb + off);
                LDMATRIX_X4(a_lo[mt], smb + 16384 + off);
            }
            #pragma unroll
            for (int np = 0; np < 2; np++) {
                uint32_t off = SWZ((uint32_t)((bRow0 + np * 16) * 128 + kb + bColOff));
                LDMATRIX_X4(b_hi[np], smb + 32768 + off);
                LDMATRIX_X4(b_lo[np], smb + 40960 + off);
            }
            #pragma unroll
            for (int mt = 0; mt < 2; mt++)
                #pragma unroll
                for (int nt = 0; nt < 4; nt++) {
                    const int np = nt >> 1, hb = (nt & 1) * 2;
                    MMA_BF16(acc[mt][nt], a_hi[mt], b_hi[np][hb], b_hi[np][hb + 1]);
                    MMA_BF16(acc[mt][nt], a_hi[mt], b_lo[np][hb], b_lo[np][hb + 1]);
                    MMA_BF16(acc[mt][nt], a_lo[mt], b_hi[np][hb], b_hi[np][hb + 1]);
                }
        }
        __syncthreads();
    }

    #pragma unroll
    for (int mt = 0; mt < 2; mt++)
        #pragma unroll
        for (int nt = 0; nt < 4; nt++) {
            const long rbase = row0 + m0 + mt * 16 + (lane >> 2);
            const long col = col0 + n0w + nt * 8 + (lane & 3) * 2;
            float b0f = bias[col], b1f = bias[col + 1];
            #pragma unroll
            for (int half = 0; half < 2; half++) {
                const long r = rbase + half * 8;
                float v0 = acc[mt][nt][half * 2 + 0] + b0f;
                float v1 = acc[mt][nt][half * 2 + 1] + b1f;
                if (EPI == 2) { v0 = fmaxf(v0, 0.f); v1 = fmaxf(v1, 0.f); }
                const size_t dst = (size_t)(r * ldc + col);
                if (Cf) *(float2*)(Cf + dst) = make_float2(v0, v1);
                if (OUT_PLANES) {
                    uint32_t hi, lo;
                    pack_split2(v0, v1, hi, lo);
                    *(uint32_t*)(Chi + dst) = hi;
                    *(uint32_t*)(Clo + dst) = lo;
                }
            }
        }
}

// ===================== fused flash attention =====================
__global__ __launch_bounds__(256) void flash_attn_kernel(
    const __nv_bfloat16* __restrict__ qkvh, const __nv_bfloat16* __restrict__ qkvl,
    const __nv_bfloat16* __restrict__ vth_, const __nv_bfloat16* __restrict__ vtl_,
    __nv_bfloat16* __restrict__ ch_, __nv_bfloat16* __restrict__ cl_)
{
    extern __shared__ __align__(16) char sm[];
    const uint32_t smb = smem_to_u32(sm);
    const int tid = threadIdx.x, lane = tid & 31, wid = tid >> 5;
    const int bh = blockIdx.y;
    const int b = bh >> 3, h = bh & 7;
    const int q0 = blockIdx.x * 128;

    const __nv_bfloat16* qhp = qkvh + (size_t)(b * SS + q0) * QKVLD + h * 64;
    const __nv_bfloat16* qlp = qkvl + (size_t)(b * SS + q0) * QKVLD + h * 64;
    const __nv_bfloat16* khp = qkvh + (size_t)b * SS * QKVLD + 512 + h * 64;
    const __nv_bfloat16* klp = qkvl + (size_t)b * SS * QKVLD + 512 + h * 64;
    const __nv_bfloat16* vthp = vth_ + (size_t)bh * 64 * SS;
    const __nv_bfloat16* vtlp = vtl_ + (size_t)bh * 64 * SS;

    #pragma unroll
    for (int t = 0; t < 4; t++) {
        int i = tid + t * 256;
        int r = i >> 3, seg = i & 7;
        uint32_t off = SWZ((uint32_t)(r * 128 + seg * 16));
        *(float4*)(sm + off)         = *(const float4*)(qhp + (size_t)r * QKVLD + seg * 8);
        *(float4*)(sm + 16384 + off) = *(const float4*)(qlp + (size_t)r * QKVLD + seg * 8);
    }
    __syncthreads();
    uint32_t qfh[4][4], qfl[4][4];
    {
        const int aRow = wid * 16 + (lane & 15);
        const int aCol = (lane >> 4) << 4;
        #pragma unroll
        for (int ks = 0; ks < 4; ks++) {
            uint32_t off = SWZ((uint32_t)(aRow * 128 + ks * 32 + aCol));
            LDMATRIX_X4(qfh[ks], smb + off);
            LDMATRIX_X4(qfl[ks], smb + 16384 + off);
        }
    }
    __syncthreads();

    const int bRow = (lane & 7) + ((lane >> 4) & 1) * 8;
    const int bCol = ((lane >> 3) & 1) << 4;

    float acc_o[8][4] = {};
    float m0r = -1e30f, m1r = -1e30f, l0 = 0.f, l1 = 0.f;

    auto load_tile = [&](int it, int buf) {
        const int kv0 = it * 64;
        const uint32_t base = smb + buf * 32768;
        #pragma unroll
        for (int t = 0; t < 8; t++) {
            int i = tid + t * 256;
            int plane = i >> 9;
            int r = (i >> 3) & 63;
            int seg = i & 7;
            uint32_t dst = base + plane * 8192 + SWZ((uint32_t)(r * 128 + seg * 16));
            const __nv_bfloat16* src;
            if (plane == 0)      src = khp  + (size_t)(kv0 + r) * QKVLD + seg * 8;
            else if (plane == 1) src = klp  + (size_t)(kv0 + r) * QKVLD + seg * 8;
            else if (plane == 2) src = vthp + (size_t)r * SS + kv0 + seg * 8;
            else                 src = vtlp + (size_t)r * SS + kv0 + seg * 8;
            CP_ASYNC16(dst, src);
        }
        CP_COMMIT();
    };

    load_tile(0, 0);

    const int NIT = SS / 64;
    for (int it = 0; it < NIT; it++) {
        const int buf = it & 1;
        if (it + 1 < NIT) { load_tile(it + 1, buf ^ 1); CP_WAIT(1); }
        else               { CP_WAIT(0); }
        __syncthreads();

        const uint32_t kbase = smb + buf * 32768;
        const uint32_t vbase = kbase + 16384;

        float s[8][4] = {};
        #pragma unroll
        for (int ks = 0; ks < 4; ks++) {
            uint32_t bhf[4][4], blf[4][4];
            #pragma unroll
            for (int np = 0; np < 4; np++) {
                uint32_t off = SWZ((uint32_t)((np * 16 + bRow) * 128 + ks * 32 + bCol));
                LDMATRIX_X4(bhf[np], kbase + off);
                LDMATRIX_X4(blf[np], kbase + 8192 + off);
            }
            #pragma unroll
            for (int nt = 0; nt < 8; nt++) {
                const int np = nt >> 1, hb = (nt & 1) * 2;
                MMA_BF16(s[nt], qfh[ks], bhf[np][hb], bhf[np][hb + 1]);
                MMA_BF16(s[nt], qfh[ks], blf[np][hb], blf[np][hb + 1]);
                MMA_BF16(s[nt], qfl[ks], bhf[np][hb], bhf[np][hb + 1]);
            }
        }

        float mx0 = -1e30f, mx1 = -1e30f;
        #pragma unroll
        for (int t = 0; t < 8; t++) {
            mx0 = fmaxf(mx0, fmaxf(s[t][0], s[t][1]));
            mx1 = fmaxf(mx1, fmaxf(s[t][2], s[t][3]));
        }
        mx0 = fmaxf(mx0, __shfl_xor_sync(0xffffffffu, mx0, 1));
        mx0 = fmaxf(mx0, __shfl_xor_sync(0xffffffffu, mx0, 2));
        mx1 = fmaxf(mx1, __shfl_xor_sync(0xffffffffu, mx1, 1));
        mx1 = fmaxf(mx1, __shfl_xor_sync(0xffffffffu, mx1, 2));

        const float mn0 = fmaxf(m0r, 0.125f * mx0);
        const float mn1 = fmaxf(m1r, 0.125f * mx1);
        const float alpha0 = __expf(m0r - mn0);
        const float alpha1 = __expf(m1r - mn1);
        m0r = mn0; m1r = mn1;

        float sum0 = 0.f, sum1 = 0.f;
        #pragma unroll
        for (int t = 0; t < 8; t++) {
            float p0 = __expf(fmaf(0.125f, s[t][0], -mn0));
            float p1 = __expf(fmaf(0.125f, s[t][1], -mn0));
            float p2 = __expf(fmaf(0.125f, s[t][2], -mn1));
            float p3 = __expf(fmaf(0.125f, s[t][3], -mn1));
            sum0 += p0 + p1; sum1 += p2 + p3;
            s[t][0] = p0; s[t][1] = p1; s[t][2] = p2; s[t][3] = p3;
        }
        sum0 += __shfl_xor_sync(0xffffffffu, sum0, 1);
        sum0 += __shfl_xor_sync(0xffffffffu, sum0, 2);
        sum1 += __shfl_xor_sync(0xffffffffu, sum1, 1);
        sum1 += __shfl_xor_sync(0xffffffffu, sum1, 2);
        l0 = l0 * alpha0 + sum0;
        l1 = l1 * alpha1 + sum1;
        #pragma unroll
        for (int t = 0; t < 8; t++) {
            acc_o[t][0] *= alpha0; acc_o[t][1] *= alpha0;
            acc_o[t][2] *= alpha1; acc_o[t][3] *= alpha1;
        }

        #pragma unroll
        for (int j = 0; j < 4; j++) {
            uint32_t pa_h[4], pa_l[4];
            pack_split2(s[2*j][0],   s[2*j][1],   pa_h[0], pa_l[0]);
            pack_split2(s[2*j][2],   s[2*j][3],   pa_h[1], pa_l[1]);
            pack_split2(s[2*j+1][0], s[2*j+1][1], pa_h[2], pa_l[2]);
            pack_split2(s[2*j+1][2], s[2*j+1][3], pa_h[3], pa_l[3]);

            uint32_t vhf[4][4], vlf[4][4];
            #pragma unroll
            for (int np = 0; np < 4; np++) {
                uint32_t off = SWZ((uint32_t)((np * 16 + bRow) * 128 + j * 32 + bCol));
                LDMATRIX_X4(vhf[np], vbase + off);
                LDMATRIX_X4(vlf[np], vbase + 8192 + off);
            }
            #pragma unroll
            for (int nt = 0; nt < 8; nt++) {
                const int np = nt >> 1, hb = (nt & 1) * 2;
                MMA_BF16(acc_o[nt], pa_h, vhf[np][hb], vhf[np][hb + 1]);
                MMA_BF16(acc_o[nt], pa_h, vlf[np][hb], vlf[np][hb + 1]);
                MMA_BF16(acc_o[nt], pa_l, vhf[np][hb], vhf[np][hb + 1]);
            }
        }
        __syncthreads();
    }

    const float inv0 = 1.0f / l0;
    const float inv1 = 1.0f / l1;
    const size_t tok0 = (size_t)(b * SS + q0 + wid * 16 + (lane >> 2)) * DM + h * 64;
    #pragma unroll
    for (int t = 0; t < 8; t++) {
        const int dcol = t * 8 + (lane & 3) * 2;
        uint32_t hi, lo;
        pack_split2(acc_o[t][0] * inv0, acc_o[t][1] * inv0, hi, lo);
        *(uint32_t*)(ch_ + tok0 + dcol) = hi;
        *(uint32_t*)(cl_ + tok0 + dcol) = lo;
        pack_split2(acc_o[t][2] * inv1, acc_o[t][3] * inv1, hi, lo);
        *(uint32_t*)(ch_ + tok0 + 8 * DM + dcol) = hi;
        *(uint32_t*)(cl_ + tok0 + 8 * DM + dcol) = lo;
    }
}

// ===================== add + LayerNorm =====================
template<bool PLANES>
__global__ void add_ln_kernel(const float* __restrict__ xa, const float* __restrict__ xb,
                              const float* __restrict__ g, const float* __restrict__ be,
                              float* __restrict__ out,
                              __nv_bfloat16* __restrict__ ohi, __nv_bfloat16* __restrict__ olo)
{
    __shared__ float red[256];
    const int row = blockIdx.x;
    const int t = threadIdx.x;
    const float* pa = xa + (size_t)row * DM;
    const float* pb = xb + (size_t)row * DM;

    float v0 = pa[t] + pb[t];
    float v1 = pa[t + 256] + pb[t + 256];

    red[t] = v0 + v1; __syncthreads();
    for (int s = 128; s > 0; s >>= 1) {
        if (t < s) red[t] += red[t + s];
        __syncthreads();
    }
    float mu = red[0] * (1.0f / DM); __syncthreads();

    float d0 = v0 - mu, d1 = v1 - mu;
    red[t] = d0 * d0 + d1 * d1; __syncthreads();
    for (int s = 128; s > 0; s >>= 1) {
        if (t < s) red[t] += red[t + s];
        __syncthreads();
    }
    float r = rsqrtf(red[0] * (1.0f / DM) + 1e-5f);

    float o0 = d0 * r * g[t] + be[t];
    float o1 = d1 * r * g[t + 256] + be[t + 256];
    out[(size_t)row * DM + t] = o0;
    out[(size_t)row * DM + t + 256] = o1;
    if (PLANES) {
        __nv_bfloat16 h, l;
        split_bf16(o0, h, l); ohi[(size_t)row * DM + t] = h;       olo[(size_t)row * DM + t] = l;
        split_bf16(o1, h, l); ohi[(size_t)row * DM + t + 256] = h; olo[(size_t)row * DM + t + 256] = l;
    }
}

// ===================== launch =====================
extern "C" void kernel_launch(void* const* d_in, const int* in_sizes, int n_in,
                              void* d_out, int out_size)
{
    const float* x   = (const float*)d_in[0];
    const float* Wq  = (const float*)d_in[1];
    const float* bq  = (const float*)d_in[2];
    const float* Wk  = (const float*)d_in[3];
    const float* bk  = (const float*)d_in[4];
    const float* Wv  = (const float*)d_in[5];
    const float* bv  = (const float*)d_in[6];
    const float* Wo  = (const float*)d_in[7];
    const float* bo  = (const float*)d_in[8];
    const float* W1  = (const float*)d_in[9];
    const float* b1  = (const float*)d_in[10];
    const float* W2  = (const float*)d_in[11];
    const float* b2  = (const float*)d_in[12];
    const float* g1  = (const float*)d_in[13];
    const float* be1 = (const float*)d_in[14];
    const float* g2  = (const float*)d_in[15];
    const float* be2 = (const float*)d_in[16];

    #define SYM(p, s) cudaGetSymbolAddress((void**)&p, s)
    float *ao, *hbuf, *ff2, *bqkv;
    __nv_bfloat16 *xh,*xl,*qkh,*qkl,*vth,*vtl,*ch,*cl,*hh,*hl,*f1h,*f1l;
    __nv_bfloat16 *wqkvh,*wqkvl,*woh,*wol,*w1h,*w1l,*w2h,*w2l;
    SYM(ao, g_ao); SYM(hbuf, g_h); SYM(ff2, g_ff2); SYM(bqkv, g_bqkv);
    SYM(xh, g_x_hi); SYM(xl, g_x_lo);
    SYM(qkh, g_qkv_hi); SYM(qkl, g_qkv_lo);
    SYM(vth, g_vt_hi); SYM(vtl, g_vt_lo);
    SYM(ch, g_ctx_hi); SYM(cl, g_ctx_lo);
    SYM(hh, g_h_hi); SYM(hl, g_h_lo);
    SYM(f1h, g_f1_hi); SYM(f1l, g_f1_lo);
    SYM(wqkvh, g_wqkv_hi); SYM(wqkvl, g_wqkv_lo);
    SYM(woh, g_wo_hi); SYM(wol, g_wo_lo);
    SYM(w1h, g_w1_hi); SYM(w1l, g_w1_lo);
    SYM(w2h, g_w2_hi); SYM(w2l, g_w2_lo);
    #undef SYM

    cudaFuncSetAttribute(flash_attn_kernel,
                         cudaFuncAttributeMaxDynamicSharedMemorySize, 65536);

    // launches 1-5 (ncu -s 5 skips these; launch 6 = QKV GEMM gets profiled)
    cvt_kernel<<<(NT * DM + 255) / 256, 256>>>(x, xh, xl, NT * DM);                   // 1
    concat_bias_kernel<<<QKVLD / 256, 256>>>(bq, bk, bv, bqkv);                       // 2
    wtrans_kernel<<<dim3(DM / 32, DM / 32), 256>>>(Wq, DM, DM, wqkvh, wqkvl);         // 3
    wtrans_kernel<<<dim3(DM / 32, DM / 32), 256>>>(Wk, DM, DM, wqkvh + 512 * DM, wqkvl + 512 * DM);   // 4
    wtrans_kernel<<<dim3(DM / 32, DM / 32), 256>>>(Wv, DM, DM, wqkvh + 1024 * DM, wqkvl + 1024 * DM); // 5

    // 6. fused QKV projection: [4096,512] @ [512,1536]  <-- profiled launch
    mma_gemm_kernel<1, true><<<dim3(QKVLD / 64, NT / 128), 256>>>(
        xh, xl, DM, wqkvh, wqkvl, DM, bqkv, nullptr, qkh, qkl, QKVLD, DM);

    // 7. remaining weight transposes (one launch)
    wtrans3_kernel<<<2304, 256>>>(Wo, woh, wol, W1, w1h, w1l, W2, w2h, w2l);

    // 8. transpose V per head
    vtrans_kernel<<<dim3(SS / 64, BH), 256>>>(qkh, qkl, vth, vtl);

    // 9. fused flash attention -> ctx planes
    flash_attn_kernel<<<dim3(SS / 128, BH), 256, 65536>>>(
        qkh, qkl, vth, vtl, ch, cl);

    // 10. attn_out = ctx @ Wo + bo (fp32)
    mma_gemm_kernel<1, false><<<dim3(DM / 64, NT / 128), 256>>>(
        ch, cl, DM, woh, wol, DM, bo, ao, nullptr, nullptr, DM, DM);

    // 11. h = LN(x + ao)
    add_ln_kernel<true><<<NT, 256>>>(x, ao, g1, be1, hbuf, hh, hl);

    // 12. ff1 = relu(h @ W1 + b1)
    mma_gemm_kernel<2, true><<<dim3(DFF / 64, NT / 128), 256>>>(
        hh, hl, DM, w1h, w1l, DM, b1, nullptr, f1h, f1l, DFF, DM);

    // 13. ff2 = ff1 @ W2 + b2 (fp32)
    mma_gemm_kernel<1, false><<<dim3(DM / 64, NT / 128), 256>>>(
        f1h, f1l, DFF, w2h, w2l, DFF, b2, ff2, nullptr, nullptr, DM, DFF);

    // 14. out = LN(h + ff2)
    add_ln_kernel<false><<<NT, 256>>>(hbuf, ff2, g2, be2, (float*)d_out, nullptr, nullptr);
}

// round 8
// speedup vs baseline: 1.9874x; 1.8693x over previous
#include <cuda_runtime.h>
#include <cuda_fp16.h>
#include <cstdint>
#include <math.h>

#define DM 512
#define NH 8
#define HD 64
#define DFF 2048
#define BB 2
#define SS 2048
#define NT (BB*SS)
#define BH (BB*NH)
#define QKVLD 1536

#define SWZ(off) ((off) ^ (((off) >> 3) & 0x70))

__device__ __forceinline__ uint32_t smem_to_u32(const void* smem_ptr) {
    uint32_t addr;
    asm("{ .reg .u64 tmp; cvta.to.shared.u64 tmp, %1; cvt.u32.u64 %0, tmp; }"
        : "=r"(addr) : "l"(smem_ptr));
    return addr;
}

#define LDMATRIX_X4(r, addr) \
    asm volatile("ldmatrix.sync.aligned.m8n8.x4.shared.b16 {%0,%1,%2,%3}, [%4];" \
        : "=r"((r)[0]), "=r"((r)[1]), "=r"((r)[2]), "=r"((r)[3]) : "r"(addr))

#define MMA_F16(c, a, b0, b1) \
    asm volatile("mma.sync.aligned.m16n8k16.row.col.f32.f16.f16.f32 " \
        "{%0,%1,%2,%3}, {%4,%5,%6,%7}, {%8,%9}, {%0,%1,%2,%3};" \
        : "+f"((c)[0]), "+f"((c)[1]), "+f"((c)[2]), "+f"((c)[3]) \
        : "r"((a)[0]), "r"((a)[1]), "r"((a)[2]), "r"((a)[3]), "r"(b0), "r"(b1))

#define CP_ASYNC16(dst, src) \
    asm volatile("cp.async.cg.shared.global [%0], [%1], 16;" :: "r"(dst), "l"(src))
#define CP_COMMIT() asm volatile("cp.async.commit_group;" ::: "memory")
#define CP_WAIT(n)  asm volatile("cp.async.wait_group %0;" :: "n"(n) : "memory")

// ===================== static device scratch =====================
__device__ __half g_x[NT * DM];
__device__ __half g_qkv[NT * QKVLD];
__device__ __half g_vt[NT * DM];        // [bh][d][s]
__device__ __half g_ctx[NT * DM];
__device__ __half g_hh[NT * DM];
__device__ __half g_f1[NT * DFF];

__device__ __half g_wqkv[QKVLD * DM];   // [N=1536,K=512]
__device__ __half g_wo[DM * DM];
__device__ __half g_w1[DM * DFF];
__device__ __half g_w2[DM * DFF];
__device__ float g_bqkv[QKVLD];

__device__ float g_ao[NT * DM];
__device__ float g_h[NT * DM];
__device__ float g_ff2[NT * DM];

// ===================== helpers =====================
__global__ void cvt_kernel(const float* __restrict__ in, __half* __restrict__ out, int n)
{
    int i = blockIdx.x * 256 + threadIdx.x;
    if (i < n) out[i] = __float2half(in[i]);
}

__global__ void concat_bias_kernel(const float* __restrict__ a, const float* __restrict__ b,
                                   const float* __restrict__ c, float* __restrict__ o)
{
    int i = blockIdx.x * 256 + threadIdx.x;  // 0..1535
    float v = (i < 512) ? a[i] : (i < 1024) ? b[i - 512] : c[i - 1024];
    o[i] = v;
}

// W[K,N] fp32 -> WT[N,K] fp16, one 32x32 tile
__device__ __forceinline__ void wtrans_tile(const float* __restrict__ W, int K, int N,
                                            __half* __restrict__ T, int n0, int k0)
{
    __shared__ float tile[32][33];
    int tx = threadIdx.x & 31, ty = threadIdx.x >> 5;
    #pragma unroll
    for (int i = 0; i < 32; i += 8)
        tile[ty + i][tx] = W[(size_t)(k0 + ty + i) * N + n0 + tx];
    __syncthreads();
    #pragma unroll
    for (int i = 0; i < 32; i += 8)
        T[(size_t)(n0 + ty + i) * K + k0 + tx] = __float2half(tile[tx][ty + i]);
}

// all weight transposes in one launch:
// Wq/Wk/Wv (256 tiles each) -> wqkv [0,768), Wo [768,1024), W1 [1024,2048), W2 [2048,3072)
__global__ void wtransall_kernel(const float* __restrict__ Wq, const float* __restrict__ Wk,
                                 const float* __restrict__ Wv, __half* __restrict__ Wqkv,
                                 const float* __restrict__ Wo, __half* __restrict__ Woh,
                                 const float* __restrict__ W1, __half* __restrict__ W1h,
                                 const float* __restrict__ W2, __half* __restrict__ W2h)
{
    int b = blockIdx.x;
    if (b < 768) {
        int w = b >> 8;              // 0,1,2 -> q,k,v
        int j = b & 255;
        int nt = j & 15, kt = j >> 4;
        const float* W = (w == 0) ? Wq : (w == 1) ? Wk : Wv;
        wtrans_tile(W, DM, DM, Wqkv + (size_t)w * 512 * DM, nt * 32, kt * 32);
    } else if (b < 1024) {
        int j = b - 768;
        int nt = j & 15, kt = j >> 4;
        wtrans_tile(Wo, DM, DM, Woh, nt * 32, kt * 32);
    } else if (b < 2048) {
        int j = b - 1024;            // W1: N=2048 (64 ntiles), K=512 (16 ktiles)
        int nt = j & 63, kt = j >> 6;
        wtrans_tile(W1, DM, DFF, W1h, nt * 32, kt * 32);
    } else {
        int j = b - 2048;            // W2: N=512 (16 ntiles), K=2048 (64 ktiles)
        int nt = j & 15, kt = j >> 4;
        wtrans_tile(W2, DFF, DM, W2h, nt * 32, kt * 32);
    }
}

// v inside qkv buffer [token, 1024 + h*64 + d] -> vT [bh][d][s]
__global__ void vtrans_kernel(const __half* __restrict__ v, __half* __restrict__ ot)
{
    __shared__ unsigned short t[64][65];
    int bh = blockIdx.y; int b = bh >> 3, h = bh & 7;
    int s0 = blockIdx.x * 64;
    for (int i = threadIdx.x; i < 64 * 64; i += 256) {
        int r = i >> 6, c = i & 63;
        t[r][c] = ((const unsigned short*)v)[(size_t)(b * SS + s0 + r) * QKVLD + 1024 + h * 64 + c];
    }
    __syncthreads();
    for (int i = threadIdx.x; i < 64 * 64; i += 256) {
        int d = i >> 6, s = i & 63;
        ((unsigned short*)ot)[((size_t)bh * 64 + d) * SS + s0 + s] = t[s][d];
    }
}

// ===================== single-pass fp16 mma.sync GEMM =====================
// BM=128, BN=64, BK=64 (= 128B rows), static 24KB smem.
// EPI: 1 +bias, 2 +bias+relu
template<int EPI, bool OUT_HALF>
__global__ __launch_bounds__(256) void mma_gemm_kernel(
    const __half* __restrict__ A, long lda,
    const __half* __restrict__ B, long ldb,
    const float* __restrict__ bias,
    float* __restrict__ Cf, __half* __restrict__ Ch, long ldc,
    int K)
{
    __shared__ __align__(16) char sm[24576];   // A 16KB, B 8KB
    const uint32_t smb = smem_to_u32(sm);

    const int tid = threadIdx.x;
    const int lane = tid & 31;
    const int wid = tid >> 5;
    const int wr = wid >> 1;
    const int wc = wid & 1;
    const int m0 = wr * 32;
    const int n0w = wc * 32;

    const int row0 = blockIdx.y * 128;
    const int col0 = blockIdx.x * 64;

    float acc[2][4][4] = {};

    const int aRow = m0 + (lane & 15);
    const int aColOff = (lane >> 4) << 4;
    const int bRow0 = n0w + (lane & 7) + ((lane >> 4) & 1) * 8;
    const int bColOff = ((lane >> 3) & 1) << 4;

    const int nchunks = K >> 6;
    for (int chunk = 0; chunk < nchunks; chunk++) {
        const int c0k = chunk << 6;
        // A tile: 128 rows x 128B = 1024 x 16B
        #pragma unroll
        for (int t = 0; t < 4; t++) {
            int i = tid + t * 256;
            int r = i >> 3, seg = i & 7;
            *(float4*)(sm + SWZ((uint32_t)(r * 128 + seg * 16))) =
                *(const float4*)(A + (size_t)(row0 + r) * lda + c0k + seg * 8);
        }
        // B tile: 64 rows x 128B = 512 x 16B
        #pragma unroll
        for (int t = 0; t < 2; t++) {
            int i = tid + t * 256;
            int r = i >> 3, seg = i & 7;
            *(float4*)(sm + 16384 + SWZ((uint32_t)(r * 128 + seg * 16))) =
                *(const float4*)(B + (size_t)(col0 + r) * ldb + c0k + seg * 8);
        }
        __syncthreads();

        #pragma unroll
        for (int ks = 0; ks < 4; ks++) {
            const int kb = ks * 32;
            uint32_t a[2][4], b[2][4];
            #pragma unroll
            for (int mt = 0; mt < 2; mt++)
                LDMATRIX_X4(a[mt], smb + SWZ((uint32_t)((aRow + mt * 16) * 128 + kb + aColOff)));
            #pragma unroll
            for (int np = 0; np < 2; np++)
                LDMATRIX_X4(b[np], smb + 16384 + SWZ((uint32_t)((bRow0 + np * 16) * 128 + kb + bColOff)));
            #pragma unroll
            for (int mt = 0; mt < 2; mt++)
                #pragma unroll
                for (int nt = 0; nt < 4; nt++) {
                    const int np = nt >> 1, hb = (nt & 1) * 2;
                    MMA_F16(acc[mt][nt], a[mt], b[np][hb], b[np][hb + 1]);
                }
        }
        __syncthreads();
    }

    #pragma unroll
    for (int mt = 0; mt < 2; mt++)
        #pragma unroll
        for (int nt = 0; nt < 4; nt++) {
            const long rbase = row0 + m0 + mt * 16 + (lane >> 2);
            const long col = col0 + n0w + nt * 8 + (lane & 3) * 2;
            float b0f = bias[col], b1f = bias[col + 1];
            #pragma unroll
            for (int half = 0; half < 2; half++) {
                const long r = rbase + half * 8;
                float v0 = acc[mt][nt][half * 2 + 0] + b0f;
                float v1 = acc[mt][nt][half * 2 + 1] + b1f;
                if (EPI == 2) { v0 = fmaxf(v0, 0.f); v1 = fmaxf(v1, 0.f); }
                const size_t dst = (size_t)(r * ldc + col);
                if (Cf) *(float2*)(Cf + dst) = make_float2(v0, v1);
                if (OUT_HALF) {
                    __half2 hv = __floats2half2_rn(v0, v1);
                    *(__half2*)(Ch + dst) = hv;
                }
            }
        }
}

// ===================== fused flash attention (fp16, single pass) =====================
__global__ __launch_bounds__(256) void flash_attn_kernel(
    const __half* __restrict__ qkv, const __half* __restrict__ vt_,
    __half* __restrict__ ctx_)
{
    __shared__ __align__(16) char sm[32768];
    const uint32_t smb = smem_to_u32(sm);
    const int tid = threadIdx.x, lane = tid & 31, wid = tid >> 5;
    const int bh = blockIdx.y;
    const int b = bh >> 3, h = bh & 7;
    const int q0 = blockIdx.x * 128;

    const __half* qp  = qkv + (size_t)(b * SS + q0) * QKVLD + h * 64;
    const __half* kp  = qkv + (size_t)b * SS * QKVLD + 512 + h * 64;
    const __half* vtp = vt_ + (size_t)bh * 64 * SS;

    // ---- stage Q (128 x 64 fp16 = 16KB), grab fragments ----
    #pragma unroll
    for (int t = 0; t < 4; t++) {
        int i = tid + t * 256;
        int r = i >> 3, seg = i & 7;
        *(float4*)(sm + SWZ((uint32_t)(r * 128 + seg * 16))) =
            *(const float4*)(qp + (size_t)r * QKVLD + seg * 8);
    }
    __syncthreads();
    uint32_t qf[4][4];
    {
        const int aRow = wid * 16 + (lane & 15);
        const int aCol = (lane >> 4) << 4;
        #pragma unroll
        for (int ks = 0; ks < 4; ks++)
            LDMATRIX_X4(qf[ks], smb + SWZ((uint32_t)(aRow * 128 + ks * 32 + aCol)));
    }
    __syncthreads();

    const int bRow = (lane & 7) + ((lane >> 4) & 1) * 8;
    const int bCol = ((lane >> 3) & 1) << 4;

    float acc_o[8][4] = {};
    float m0r = -1e30f, m1r = -1e30f, l0 = 0.f, l1 = 0.f;

    auto load_tile = [&](int it, int buf) {
        const int kv0 = it * 64;
        const uint32_t base = smb + buf * 16384;
        #pragma unroll
        for (int t = 0; t < 4; t++) {
            int i = tid + t * 256;       // 0..1023
            int plane = i >> 9;          // 0 = K, 1 = V
            int r = (i >> 3) & 63;
            int seg = i & 7;
            uint32_t dst = base + plane * 8192 + SWZ((uint32_t)(r * 128 + seg * 16));
            const __half* src = plane ? (vtp + (size_t)r * SS + kv0 + seg * 8)
                                      : (kp + (size_t)(kv0 + r) * QKVLD + seg * 8);
            CP_ASYNC16(dst, src);
        }
        CP_COMMIT();
    };

    load_tile(0, 0);

    const int NIT = SS / 64;
    for (int it = 0; it < NIT; it++) {
        const int buf = it & 1;
        if (it + 1 < NIT) { load_tile(it + 1, buf ^ 1); CP_WAIT(1); }
        else               { CP_WAIT(0); }
        __syncthreads();

        const uint32_t kbase = smb + buf * 16384;
        const uint32_t vbase = kbase + 8192;

        float s[8][4] = {};
        #pragma unroll
        for (int ks = 0; ks < 4; ks++) {
            uint32_t bf[4][4];
            #pragma unroll
            for (int np = 0; np < 4; np++)
                LDMATRIX_X4(bf[np], kbase + SWZ((uint32_t)((np * 16 + bRow) * 128 + ks * 32 + bCol)));
            #pragma unroll
            for (int nt = 0; nt < 8; nt++) {
                const int np = nt >> 1, hb = (nt & 1) * 2;
                MMA_F16(s[nt], qf[ks], bf[np][hb], bf[np][hb + 1]);
            }
        }

        float mx0 = -1e30f, mx1 = -1e30f;
        #pragma unroll
        for (int t = 0; t < 8; t++) {
            mx0 = fmaxf(mx0, fmaxf(s[t][0], s[t][1]));
            mx1 = fmaxf(mx1, fmaxf(s[t][2], s[t][3]));
        }
        mx0 = fmaxf(mx0, __shfl_xor_sync(0xffffffffu, mx0, 1));
        mx0 = fmaxf(mx0, __shfl_xor_sync(0xffffffffu, mx0, 2));
        mx1 = fmaxf(mx1, __shfl_xor_sync(0xffffffffu, mx1, 1));
        mx1 = fmaxf(mx1, __shfl_xor_sync(0xffffffffu, mx1, 2));

        const float mn0 = fmaxf(m0r, 0.125f * mx0);
        const float mn1 = fmaxf(m1r, 0.125f * mx1);
        const float alpha0 = __expf(m0r - mn0);
        const float alpha1 = __expf(m1r - mn1);
        m0r = mn0; m1r = mn1;

        float sum0 = 0.f, sum1 = 0.f;
        #pragma unroll
        for (int t = 0; t < 8; t++) {
            float p0 = __expf(fmaf(0.125f, s[t][0], -mn0));
            float p1 = __expf(fmaf(0.125f, s[t][1], -mn0));
            float p2 = __expf(fmaf(0.125f, s[t][2], -mn1));
            float p3 = __expf(fmaf(0.125f, s[t][3], -mn1));
            sum0 += p0 + p1; sum1 += p2 + p3;
            s[t][0] = p0; s[t][1] = p1; s[t][2] = p2; s[t][3] = p3;
        }
        sum0 += __shfl_xor_sync(0xffffffffu, sum0, 1);
        sum0 += __shfl_xor_sync(0xffffffffu, sum0, 2);
        sum1 += __shfl_xor_sync(0xffffffffu, sum1, 1);
        sum1 += __shfl_xor_sync(0xffffffffu, sum1, 2);
        l0 = l0 * alpha0 + sum0;
        l1 = l1 * alpha1 + sum1;
        #pragma unroll
        for (int t = 0; t < 8; t++) {
            acc_o[t][0] *= alpha0; acc_o[t][1] *= alpha0;
            acc_o[t][2] *= alpha1; acc_o[t][3] *= alpha1;
        }

        #pragma unroll
        for (int j = 0; j < 4; j++) {
            uint32_t pa[4];
            __half2 h0 = __floats2half2_rn(s[2*j][0],   s[2*j][1]);
            __half2 h1 = __floats2half2_rn(s[2*j][2],   s[2*j][3]);
            __half2 h2 = __floats2half2_rn(s[2*j+1][0], s[2*j+1][1]);
            __half2 h3 = __floats2half2_rn(s[2*j+1][2], s[2*j+1][3]);
            pa[0] = *(uint32_t*)&h0; pa[1] = *(uint32_t*)&h1;
            pa[2] = *(uint32_t*)&h2; pa[3] = *(uint32_t*)&h3;

            uint32_t vf[4][4];
            #pragma unroll
            for (int np = 0; np < 4; np++)
                LDMATRIX_X4(vf[np], vbase + SWZ((uint32_t)((np * 16 + bRow) * 128 + j * 32 + bCol)));
            #pragma unroll
            for (int nt = 0; nt < 8; nt++) {
                const int np = nt >> 1, hb = (nt & 1) * 2;
                MMA_F16(acc_o[nt], pa, vf[np][hb], vf[np][hb + 1]);
            }
        }
        __syncthreads();
    }

    const float inv0 = 1.0f / l0;
    const float inv1 = 1.0f / l1;
    const size_t tok0 = (size_t)(b * SS + q0 + wid * 16 + (lane >> 2)) * DM + h * 64;
    #pragma unroll
    for (int t = 0; t < 8; t++) {
        const int dcol = t * 8 + (lane & 3) * 2;
        __half2 o0 = __floats2half2_rn(acc_o[t][0] * inv0, acc_o[t][1] * inv0);
        __half2 o1 = __floats2half2_rn(acc_o[t][2] * inv1, acc_o[t][3] * inv1);
        *(__half2*)(ctx_ + tok0 + dcol) = o0;
        *(__half2*)(ctx_ + tok0 + 8 * DM + dcol) = o1;
    }
}

// ===================== add + LayerNorm =====================
template<bool OUT_HALF>
__global__ void add_ln_kernel(const float* __restrict__ xa, const float* __restrict__ xb,
                              const float* __restrict__ g, const float* __restrict__ be,
                              float* __restrict__ out, __half* __restrict__ oh)
{
    __shared__ float red[256];
    const int row = blockIdx.x;
    const int t = threadIdx.x;
    const float* pa = xa + (size_t)row * DM;
    const float* pb = xb + (size_t)row * DM;

    float v0 = pa[t] + pb[t];
    float v1 = pa[t + 256] + pb[t + 256];

    red[t] = v0 + v1; __syncthreads();
    for (int s = 128; s > 0; s >>= 1) {
        if (t < s) red[t] += red[t + s];
        __syncthreads();
    }
    float mu = red[0] * (1.0f / DM); __syncthreads();

    float d0 = v0 - mu, d1 = v1 - mu;
    red[t] = d0 * d0 + d1 * d1; __syncthreads();
    for (int s = 128; s > 0; s >>= 1) {
        if (t < s) red[t] += red[t + s];
        __syncthreads();
    }
    float r = rsqrtf(red[0] * (1.0f / DM) + 1e-5f);

    float o0 = d0 * r * g[t] + be[t];
    float o1 = d1 * r * g[t + 256] + be[t + 256];
    out[(size_t)row * DM + t] = o0;
    out[(size_t)row * DM + t + 256] = o1;
    if (OUT_HALF) {
        oh[(size_t)row * DM + t] = __float2half(o0);
        oh[(size_t)row * DM + t + 256] = __float2half(o1);
    }
}

// ===================== launch =====================
extern "C" void kernel_launch(void* const* d_in, const int* in_sizes, int n_in,
                              void* d_out, int out_size)
{
    const float* x   = (const float*)d_in[0];
    const float* Wq  = (const float*)d_in[1];
    const float* bq  = (const float*)d_in[2];
    const float* Wk  = (const float*)d_in[3];
    const float* bk  = (const float*)d_in[4];
    const float* Wv  = (const float*)d_in[5];
    const float* bv  = (const float*)d_in[6];
    const float* Wo  = (const float*)d_in[7];
    const float* bo  = (const float*)d_in[8];
    const float* W1  = (const float*)d_in[9];
    const float* b1  = (const float*)d_in[10];
    const float* W2  = (const float*)d_in[11];
    const float* b2  = (const float*)d_in[12];
    const float* g1  = (const float*)d_in[13];
    const float* be1 = (const float*)d_in[14];
    const float* g2  = (const float*)d_in[15];
    const float* be2 = (const float*)d_in[16];

    #define SYM(p, s) cudaGetSymbolAddress((void**)&p, s)
    float *ao, *hbuf, *ff2, *bqkv;
    __half *xh, *qkv, *vt, *ctx, *hh, *f1;
    __half *wqkv, *wo, *w1, *w2;
    SYM(ao, g_ao); SYM(hbuf, g_h); SYM(ff2, g_ff2); SYM(bqkv, g_bqkv);
    SYM(xh, g_x); SYM(qkv, g_qkv); SYM(vt, g_vt); SYM(ctx, g_ctx);
    SYM(hh, g_hh); SYM(f1, g_f1);
    SYM(wqkv, g_wqkv); SYM(wo, g_wo); SYM(w1, g_w1); SYM(w2, g_w2);
    #undef SYM

    // 1. conversions (x -> fp16; all weights transposed+converted in one launch)
    cvt_kernel<<<(NT * DM + 255) / 256, 256>>>(x, xh, NT * DM);
    concat_bias_kernel<<<QKVLD / 256, 256>>>(bq, bk, bv, bqkv);
    wtransall_kernel<<<3072, 256>>>(Wq, Wk, Wv, wqkv, Wo, wo, W1, w1, W2, w2);

    // 2. fused QKV projection: [4096,512] @ [512,1536]
    mma_gemm_kernel<1, true><<<dim3(QKVLD / 64, NT / 128), 256>>>(
        xh, DM, wqkv, DM, bqkv, nullptr, qkv, QKVLD, DM);

    // 3. transpose V per head
    vtrans_kernel<<<dim3(SS / 64, BH), 256>>>(qkv, vt);

    // 4. fused flash attention -> ctx fp16
    flash_attn_kernel<<<dim3(SS / 128, BH), 256>>>(qkv, vt, ctx);

    // 5. attn_out = ctx @ Wo + bo (fp32)
    mma_gemm_kernel<1, false><<<dim3(DM / 64, NT / 128), 256>>>(
        ctx, DM, wo, DM, bo, ao, nullptr, DM, DM);

    // 6. h = LN(x + ao)
    add_ln_kernel<true><<<NT, 256>>>(x, ao, g1, be1, hbuf, hh);

    // 7. ff1 = relu(h @ W1 + b1)
    mma_gemm_kernel<2, true><<<dim3(DFF / 64, NT / 128), 256>>>(
        hh, DM, w1, DM, b1, nullptr, f1, DFF, DM);

    // 8. ff2 = ff1 @ W2 + b2 (fp32)
    mma_gemm_kernel<1, false><<<dim3(DM / 64, NT / 128), 256>>>(
        f1, DFF, w2, DFF, b2, ff2, nullptr, DM, DFF);

    // 9. out = LN(h + ff2)
    add_ln_kernel<false><<<NT, 256>>>(hbuf, ff2, g2, be2, (float*)d_out, nullptr);
}

// round 9
// speedup vs baseline: 2.3886x; 1.2018x over previous
#include <cuda_runtime.h>
#include <cuda_fp16.h>
#include <cstdint>
#include <math.h>

#define DM 512
#define NH 8
#define HD 64
#define DFF 2048
#define BB 2
#define SS 2048
#define NT (BB*SS)
#define BH (BB*NH)
#define QKVLD 1536

#define SWZ(off) ((off) ^ (((off) >> 3) & 0x70))

__device__ __forceinline__ uint32_t smem_to_u32(const void* smem_ptr) {
    uint32_t addr;
    asm("{ .reg .u64 tmp; cvta.to.shared.u64 tmp, %1; cvt.u32.u64 %0, tmp; }"
        : "=r"(addr) : "l"(smem_ptr));
    return addr;
}

#define LDMATRIX_X4(r, addr) \
    asm volatile("ldmatrix.sync.aligned.m8n8.x4.shared.b16 {%0,%1,%2,%3}, [%4];" \
        : "=r"((r)[0]), "=r"((r)[1]), "=r"((r)[2]), "=r"((r)[3]) : "r"(addr))

#define MMA_F16(c, a, b0, b1) \
    asm volatile("mma.sync.aligned.m16n8k16.row.col.f32.f16.f16.f32 " \
        "{%0,%1,%2,%3}, {%4,%5,%6,%7}, {%8,%9}, {%0,%1,%2,%3};" \
        : "+f"((c)[0]), "+f"((c)[1]), "+f"((c)[2]), "+f"((c)[3]) \
        : "r"((a)[0]), "r"((a)[1]), "r"((a)[2]), "r"((a)[3]), "r"(b0), "r"(b1))

#define CP_ASYNC16(dst, src) \
    asm volatile("cp.async.cg.shared.global [%0], [%1], 16;" :: "r"(dst), "l"(src))
#define CP_COMMIT() asm volatile("cp.async.commit_group;" ::: "memory")
#define CP_WAIT(n)  asm volatile("cp.async.wait_group %0;" :: "n"(n) : "memory")

// ===================== static device scratch =====================
__device__ __half g_x[NT * DM];
__device__ __half g_qkv[NT * QKVLD];
__device__ __half g_vt[NT * DM];        // [bh][d][s]
__device__ __half g_ctx[NT * DM];
__device__ __half g_hh[NT * DM];
__device__ __half g_f1[NT * DFF];

__device__ __half g_wqkv[QKVLD * DM];   // [N=1536,K=512]
__device__ __half g_wo[DM * DM];
__device__ __half g_w1[DM * DFF];
__device__ __half g_w2[DM * DFF];
__device__ float g_bqkv[QKVLD];

__device__ float g_ao[NT * DM];
__device__ float g_h[NT * DM];
__device__ float g_ff2[NT * DM];

// ===================== helpers =====================
__global__ void cvt_kernel(const float* __restrict__ in, __half* __restrict__ out, int n)
{
    int i = blockIdx.x * 256 + threadIdx.x;
    if (i < n) out[i] = __float2half(in[i]);
}

__global__ void concat_bias_kernel(const float* __restrict__ a, const float* __restrict__ b,
                                   const float* __restrict__ c, float* __restrict__ o)
{
    int i = blockIdx.x * 256 + threadIdx.x;  // 0..1535
    float v = (i < 512) ? a[i] : (i < 1024) ? b[i - 512] : c[i - 1024];
    o[i] = v;
}

// W[K,N] fp32 -> WT[N,K] fp16, one 32x32 tile
__device__ __forceinline__ void wtrans_tile(const float* __restrict__ W, int K, int N,
                                            __half* __restrict__ T, int n0, int k0)
{
    __shared__ float tile[32][33];
    int tx = threadIdx.x & 31, ty = threadIdx.x >> 5;
    #pragma unroll
    for (int i = 0; i < 32; i += 8)
        tile[ty + i][tx] = W[(size_t)(k0 + ty + i) * N + n0 + tx];
    __syncthreads();
    #pragma unroll
    for (int i = 0; i < 32; i += 8)
        T[(size_t)(n0 + ty + i) * K + k0 + tx] = __float2half(tile[tx][ty + i]);
}

// all weight transposes in one launch: QKV [0,768), Wo [768,1024), W1 [1024,2048), W2 [2048,3072)
__global__ void wtransall_kernel(const float* __restrict__ Wq, const float* __restrict__ Wk,
                                 const float* __restrict__ Wv, __half* __restrict__ Wqkv,
                                 const float* __restrict__ Wo, __half* __restrict__ Woh,
                                 const float* __restrict__ W1, __half* __restrict__ W1h,
                                 const float* __restrict__ W2, __half* __restrict__ W2h)
{
    int b = blockIdx.x;
    if (b < 768) {
        int w = b >> 8;              // 0,1,2 -> q,k,v
        int j = b & 255;
        int nt = j & 15, kt = j >> 4;
        const float* W = (w == 0) ? Wq : (w == 1) ? Wk : Wv;
        wtrans_tile(W, DM, DM, Wqkv + (size_t)w * 512 * DM, nt * 32, kt * 32);
    } else if (b < 1024) {
        int j = b - 768;
        int nt = j & 15, kt = j >> 4;
        wtrans_tile(Wo, DM, DM, Woh, nt * 32, kt * 32);
    } else if (b < 2048) {
        int j = b - 1024;            // W1: N=2048 (64 ntiles), K=512 (16 ktiles)
        int nt = j & 63, kt = j >> 6;
        wtrans_tile(W1, DM, DFF, W1h, nt * 32, kt * 32);
    } else {
        int j = b - 2048;            // W2: N=512 (16 ntiles), K=2048 (64 ktiles)
        int nt = j & 15, kt = j >> 4;
        wtrans_tile(W2, DFF, DM, W2h, nt * 32, kt * 32);
    }
}

// v inside qkv buffer [token, 1024 + h*64 + d] -> vT [bh][d][s]
__global__ void vtrans_kernel(const __half* __restrict__ v, __half* __restrict__ ot)
{
    __shared__ unsigned short t[64][65];
    int bh = blockIdx.y; int b = bh >> 3, h = bh & 7;
    int s0 = blockIdx.x * 64;
    for (int i = threadIdx.x; i < 64 * 64; i += 256) {
        int r = i >> 6, c = i & 63;
        t[r][c] = ((const unsigned short*)v)[(size_t)(b * SS + s0 + r) * QKVLD + 1024 + h * 64 + c];
    }
    __syncthreads();
    for (int i = threadIdx.x; i < 64 * 64; i += 256) {
        int d = i >> 6, s = i & 63;
        ((unsigned short*)ot)[((size_t)bh * 64 + d) * SS + s0 + s] = t[s][d];
    }
}

// ===================== fp16 mma.sync GEMM v3 =====================
// BM=128, BN=128, BK=64; 8 warps (4x2), warp tile 32x64; cp.async double-buffered.
// smem: buf*32768 + {A:0, B:16384}, total 64KB dynamic.
// EPI: 1 +bias, 2 +bias+relu
template<int EPI, bool OUT_HALF>
__global__ __launch_bounds__(256, 2) void mma_gemm_kernel(
    const __half* __restrict__ A, long lda,
    const __half* __restrict__ B, long ldb,
    const float* __restrict__ bias,
    float* __restrict__ Cf, __half* __restrict__ Ch, long ldc,
    int K)
{
    extern __shared__ __align__(16) char sm[];
    const uint32_t smb = smem_to_u32(sm);

    const int tid = threadIdx.x;
    const int lane = tid & 31;
    const int wid = tid >> 5;
    const int wr = wid >> 1;          // 0..3
    const int wc = wid & 1;           // 0..1
    const int m0 = wr * 32;
    const int n0 = wc * 64;

    const int row0 = blockIdx.y * 128;
    const int col0 = blockIdx.x * 128;

    float acc[2][8][4] = {};

    const int aRow = m0 + (lane & 15);
    const int aOff = (lane >> 4) << 4;
    const int bRow = (lane & 7) + ((lane >> 4) & 1) * 8;
    const int bOff = ((lane >> 3) & 1) << 4;

    auto load_chunk = [&](int chunk, int buf) {
        const int c0 = chunk << 6;
        const uint32_t base = smb + buf * 32768;
        #pragma unroll
        for (int t = 0; t < 8; t++) {
            int i = tid + t * 256;        // 0..2047
            int isB = i >> 10;
            int j = i & 1023;
            int r = j >> 3;               // 0..127
            int seg = j & 7;
            const __half* src = isB ? (B + (size_t)(col0 + r) * ldb + c0 + seg * 8)
                                    : (A + (size_t)(row0 + r) * lda + c0 + seg * 8);
            CP_ASYNC16(base + isB * 16384 + SWZ((uint32_t)(r * 128 + seg * 16)), src);
        }
        CP_COMMIT();
    };

    const int nchunks = K >> 6;
    load_chunk(0, 0);

    for (int chunk = 0; chunk < nchunks; chunk++) {
        const int buf = chunk & 1;
        if (chunk + 1 < nchunks) { load_chunk(chunk + 1, buf ^ 1); CP_WAIT(1); }
        else                      { CP_WAIT(0); }
        __syncthreads();

        const uint32_t abase = smb + buf * 32768;
        const uint32_t bbase = abase + 16384;

        #pragma unroll
        for (int ks = 0; ks < 4; ks++) {
            const int kb = ks * 32;
            uint32_t a[2][4], b[4][4];
            #pragma unroll
            for (int mt = 0; mt < 2; mt++)
                LDMATRIX_X4(a[mt], abase + SWZ((uint32_t)((aRow + mt * 16) * 128 + kb + aOff)));
            #pragma unroll
            for (int np = 0; np < 4; np++)
                LDMATRIX_X4(b[np], bbase + SWZ((uint32_t)((n0 + np * 16 + bRow) * 128 + kb + bOff)));
            #pragma unroll
            for (int mt = 0; mt < 2; mt++)
                #pragma unroll
                for (int nt = 0; nt < 8; nt++) {
                    const int np = nt >> 1, hb = (nt & 1) * 2;
                    MMA_F16(acc[mt][nt], a[mt], b[np][hb], b[np][hb + 1]);
                }
        }
        __syncthreads();
    }

    // ---- epilogue ----
    #pragma unroll
    for (int mt = 0; mt < 2; mt++)
        #pragma unroll
        for (int nt = 0; nt < 8; nt++) {
            const long rbase = row0 + m0 + mt * 16 + (lane >> 2);
            const long col = col0 + n0 + nt * 8 + (lane & 3) * 2;
            float b0f = bias[col], b1f = bias[col + 1];
            #pragma unroll
            for (int half = 0; half < 2; half++) {
                const long r = rbase + half * 8;
                float v0 = acc[mt][nt][half * 2 + 0] + b0f;
                float v1 = acc[mt][nt][half * 2 + 1] + b1f;
                if (EPI == 2) { v0 = fmaxf(v0, 0.f); v1 = fmaxf(v1, 0.f); }
                const size_t dst = (size_t)(r * ldc + col);
                if (Cf) *(float2*)(Cf + dst) = make_float2(v0, v1);
                if (OUT_HALF) {
                    __half2 hv = __floats2half2_rn(v0, v1);
                    *(__half2*)(Ch + dst) = hv;
                }
            }
        }
}

// ===================== fused flash attention (fp16, single pass) =====================
__global__ __launch_bounds__(256) void flash_attn_kernel(
    const __half* __restrict__ qkv, const __half* __restrict__ vt_,
    __half* __restrict__ ctx_)
{
    __shared__ __align__(16) char sm[32768];
    const uint32_t smb = smem_to_u32(sm);
    const int tid = threadIdx.x, lane = tid & 31, wid = tid >> 5;
    const int bh = blockIdx.y;
    const int b = bh >> 3, h = bh & 7;
    const int q0 = blockIdx.x * 128;

    const __half* qp  = qkv + (size_t)(b * SS + q0) * QKVLD + h * 64;
    const __half* kp  = qkv + (size_t)b * SS * QKVLD + 512 + h * 64;
    const __half* vtp = vt_ + (size_t)bh * 64 * SS;

    // ---- stage Q (128 x 64 fp16 = 16KB), grab fragments ----
    #pragma unroll
    for (int t = 0; t < 4; t++) {
        int i = tid + t * 256;
        int r = i >> 3, seg = i & 7;
        *(float4*)(sm + SWZ((uint32_t)(r * 128 + seg * 16))) =
            *(const float4*)(qp + (size_t)r * QKVLD + seg * 8);
    }
    __syncthreads();
    uint32_t qf[4][4];
    {
        const int aRow = wid * 16 + (lane & 15);
        const int aCol = (lane >> 4) << 4;
        #pragma unroll
        for (int ks = 0; ks < 4; ks++)
            LDMATRIX_X4(qf[ks], smb + SWZ((uint32_t)(aRow * 128 + ks * 32 + aCol)));
    }
    __syncthreads();

    const int bRow = (lane & 7) + ((lane >> 4) & 1) * 8;
    const int bCol = ((lane >> 3) & 1) << 4;

    float acc_o[8][4] = {};
    float m0r = -1e30f, m1r = -1e30f, l0 = 0.f, l1 = 0.f;

    auto load_tile = [&](int it, int buf) {
        const int kv0 = it * 64;
        const uint32_t base = smb + buf * 16384;
        #pragma unroll
        for (int t = 0; t < 4; t++) {
            int i = tid + t * 256;       // 0..1023
            int plane = i >> 9;          // 0 = K, 1 = V
            int r = (i >> 3) & 63;
            int seg = i & 7;
            uint32_t dst = base + plane * 8192 + SWZ((uint32_t)(r * 128 + seg * 16));
            const __half* src = plane ? (vtp + (size_t)r * SS + kv0 + seg * 8)
                                      : (kp + (size_t)(kv0 + r) * QKVLD + seg * 8);
            CP_ASYNC16(dst, src);
        }
        CP_COMMIT();
    };

    load_tile(0, 0);

    const int NIT = SS / 64;
    for (int it = 0; it < NIT; it++) {
        const int buf = it & 1;
        if (it + 1 < NIT) { load_tile(it + 1, buf ^ 1); CP_WAIT(1); }
        else               { CP_WAIT(0); }
        __syncthreads();

        const uint32_t kbase = smb + buf * 16384;
        const uint32_t vbase = kbase + 8192;

        float s[8][4] = {};
        #pragma unroll
        for (int ks = 0; ks < 4; ks++) {
            uint32_t bf[4][4];
            #pragma unroll
            for (int np = 0; np < 4; np++)
                LDMATRIX_X4(bf[np], kbase + SWZ((uint32_t)((np * 16 + bRow) * 128 + ks * 32 + bCol)));
            #pragma unroll
            for (int nt = 0; nt < 8; nt++) {
                const int np = nt >> 1, hb = (nt & 1) * 2;
                MMA_F16(s[nt], qf[ks], bf[np][hb], bf[np][hb + 1]);
            }
        }

        float mx0 = -1e30f, mx1 = -1e30f;
        #pragma unroll
        for (int t = 0; t < 8; t++) {
            mx0 = fmaxf(mx0, fmaxf(s[t][0], s[t][1]));
            mx1 = fmaxf(mx1, fmaxf(s[t][2], s[t][3]));
        }
        mx0 = fmaxf(mx0, __shfl_xor_sync(0xffffffffu, mx0, 1));
        mx0 = fmaxf(mx0, __shfl_xor_sync(0xffffffffu, mx0, 2));
        mx1 = fmaxf(mx1, __shfl_xor_sync(0xffffffffu, mx1, 1));
        mx1 = fmaxf(mx1, __shfl_xor_sync(0xffffffffu, mx1, 2));

        const float mn0 = fmaxf(m0r, 0.125f * mx0);
        const float mn1 = fmaxf(m1r, 0.125f * mx1);
        const float alpha0 = __expf(m0r - mn0);
        const float alpha1 = __expf(m1r - mn1);
        m0r = mn0; m1r = mn1;

        float sum0 = 0.f, sum1 = 0.f;
        #pragma unroll
        for (int t = 0; t < 8; t++) {
            float p0 = __expf(fmaf(0.125f, s[t][0], -mn0));
            float p1 = __expf(fmaf(0.125f, s[t][1], -mn0));
            float p2 = __expf(fmaf(0.125f, s[t][2], -mn1));
            float p3 = __expf(fmaf(0.125f, s[t][3], -mn1));
            sum0 += p0 + p1; sum1 += p2 + p3;
            s[t][0] = p0; s[t][1] = p1; s[t][2] = p2; s[t][3] = p3;
        }
        sum0 += __shfl_xor_sync(0xffffffffu, sum0, 1);
        sum0 += __shfl_xor_sync(0xffffffffu, sum0, 2);
        sum1 += __shfl_xor_sync(0xffffffffu, sum1, 1);
        sum1 += __shfl_xor_sync(0xffffffffu, sum1, 2);
        l0 = l0 * alpha0 + sum0;
        l1 = l1 * alpha1 + sum1;
        #pragma unroll
        for (int t = 0; t < 8; t++) {
            acc_o[t][0] *= alpha0; acc_o[t][1] *= alpha0;
            acc_o[t][2] *= alpha1; acc_o[t][3] *= alpha1;
        }

        #pragma unroll
        for (int j = 0; j < 4; j++) {
            uint32_t pa[4];
            __half2 h0 = __floats2half2_rn(s[2*j][0],   s[2*j][1]);
            __half2 h1 = __floats2half2_rn(s[2*j][2],   s[2*j][3]);
            __half2 h2 = __floats2half2_rn(s[2*j+1][0], s[2*j+1][1]);
            __half2 h3 = __floats2half2_rn(s[2*j+1][2], s[2*j+1][3]);
            pa[0] = *(uint32_t*)&h0; pa[1] = *(uint32_t*)&h1;
            pa[2] = *(uint32_t*)&h2; pa[3] = *(uint32_t*)&h3;

            uint32_t vf[4][4];
            #pragma unroll
            for (int np = 0; np < 4; np++)
                LDMATRIX_X4(vf[np], vbase + SWZ((uint32_t)((np * 16 + bRow) * 128 + j * 32 + bCol)));
            #pragma unroll
            for (int nt = 0; nt < 8; nt++) {
                const int np = nt >> 1, hb = (nt & 1) * 2;
                MMA_F16(acc_o[nt], pa, vf[np][hb], vf[np][hb + 1]);
            }
        }
        __syncthreads();
    }

    const float inv0 = 1.0f / l0;
    const float inv1 = 1.0f / l1;
    const size_t tok0 = (size_t)(b * SS + q0 + wid * 16 + (lane >> 2)) * DM + h * 64;
    #pragma unroll
    for (int t = 0; t < 8; t++) {
        const int dcol = t * 8 + (lane & 3) * 2;
        __half2 o0 = __floats2half2_rn(acc_o[t][0] * inv0, acc_o[t][1] * inv0);
        __half2 o1 = __floats2half2_rn(acc_o[t][2] * inv1, acc_o[t][3] * inv1);
        *(__half2*)(ctx_ + tok0 + dcol) = o0;
        *(__half2*)(ctx_ + tok0 + 8 * DM + dcol) = o1;
    }
}

// ===================== add + LayerNorm =====================
template<bool OUT_HALF>
__global__ void add_ln_kernel(const float* __restrict__ xa, const float* __restrict__ xb,
                              const float* __restrict__ g, const float* __restrict__ be,
                              float* __restrict__ out, __half* __restrict__ oh)
{
    __shared__ float red[256];
    const int row = blockIdx.x;
    const int t = threadIdx.x;
    const float* pa = xa + (size_t)row * DM;
    const float* pb = xb + (size_t)row * DM;

    float v0 = pa[t] + pb[t];
    float v1 = pa[t + 256] + pb[t + 256];

    red[t] = v0 + v1; __syncthreads();
    for (int s = 128; s > 0; s >>= 1) {
        if (t < s) red[t] += red[t + s];
        __syncthreads();
    }
    float mu = red[0] * (1.0f / DM); __syncthreads();

    float d0 = v0 - mu, d1 = v1 - mu;
    red[t] = d0 * d0 + d1 * d1; __syncthreads();
    for (int s = 128; s > 0; s >>= 1) {
        if (t < s) red[t] += red[t + s];
        __syncthreads();
    }
    float r = rsqrtf(red[0] * (1.0f / DM) + 1e-5f);

    float o0 = d0 * r * g[t] + be[t];
    float o1 = d1 * r * g[t + 256] + be[t + 256];
    out[(size_t)row * DM + t] = o0;
    out[(size_t)row * DM + t + 256] = o1;
    if (OUT_HALF) {
        oh[(size_t)row * DM + t] = __float2half(o0);
        oh[(size_t)row * DM + t + 256] = __float2half(o1);
    }
}

// ===================== launch =====================
extern "C" void kernel_launch(void* const* d_in, const int* in_sizes, int n_in,
                              void* d_out, int out_size)
{
    const float* x   = (const float*)d_in[0];
    const float* Wq  = (const float*)d_in[1];
    const float* bq  = (const float*)d_in[2];
    const float* Wk  = (const float*)d_in[3];
    const float* bk  = (const float*)d_in[4];
    const float* Wv  = (const float*)d_in[5];
    const float* bv  = (const float*)d_in[6];
    const float* Wo  = (const float*)d_in[7];
    const float* bo  = (const float*)d_in[8];
    const float* W1  = (const float*)d_in[9];
    const float* b1  = (const float*)d_in[10];
    const float* W2  = (const float*)d_in[11];
    const float* b2  = (const float*)d_in[12];
    const float* g1  = (const float*)d_in[13];
    const float* be1 = (const float*)d_in[14];
    const float* g2  = (const float*)d_in[15];
    const float* be2 = (const float*)d_in[16];

    #define SYM(p, s) cudaGetSymbolAddress((void**)&p, s)
    float *ao, *hbuf, *ff2, *bqkv;
    __half *xh, *qkv, *vt, *ctx, *hh, *f1;
    __half *wqkv, *wo, *w1, *w2;
    SYM(ao, g_ao); SYM(hbuf, g_h); SYM(ff2, g_ff2); SYM(bqkv, g_bqkv);
    SYM(xh, g_x); SYM(qkv, g_qkv); SYM(vt, g_vt); SYM(ctx, g_ctx);
    SYM(hh, g_hh); SYM(f1, g_f1);
    SYM(wqkv, g_wqkv); SYM(wo, g_wo); SYM(w1, g_w1); SYM(w2, g_w2);
    #undef SYM

    cudaFuncSetAttribute(mma_gemm_kernel<1, true>,
                         cudaFuncAttributeMaxDynamicSharedMemorySize, 65536);
    cudaFuncSetAttribute(mma_gemm_kernel<1, false>,
                         cudaFuncAttributeMaxDynamicSharedMemorySize, 65536);
    cudaFuncSetAttribute(mma_gemm_kernel<2, true>,
                         cudaFuncAttributeMaxDynamicSharedMemorySize, 65536);

    // 1. conversions
    cvt_kernel<<<(NT * DM + 255) / 256, 256>>>(x, xh, NT * DM);
    concat_bias_kernel<<<QKVLD / 256, 256>>>(bq, bk, bv, bqkv);
    wtransall_kernel<<<3072, 256>>>(Wq, Wk, Wv, wqkv, Wo, wo, W1, w1, W2, w2);

    // 2. fused QKV projection: [4096,512] @ [512,1536]
    mma_gemm_kernel<1, true><<<dim3(QKVLD / 128, NT / 128), 256, 65536>>>(
        xh, DM, wqkv, DM, bqkv, nullptr, qkv, QKVLD, DM);

    // 3. transpose V per head
    vtrans_kernel<<<dim3(SS / 64, BH), 256>>>(qkv, vt);

    // 4. fused flash attention -> ctx fp16
    flash_attn_kernel<<<dim3(SS / 128, BH), 256>>>(qkv, vt, ctx);

    // 5. attn_out = ctx @ Wo + bo (fp32)
    mma_gemm_kernel<1, false><<<dim3(DM / 128, NT / 128), 256, 65536>>>(
        ctx, DM, wo, DM, bo, ao, nullptr, DM, DM);

    // 6. h = LN(x + ao)
    add_ln_kernel<true><<<NT, 256>>>(x, ao, g1, be1, hbuf, hh);

    // 7. ff1 = relu(h @ W1 + b1)
    mma_gemm_kernel<2, true><<<dim3(DFF / 128, NT / 128), 256, 65536>>>(
        hh, DM, w1, DM, b1, nullptr, f1, DFF, DM);

    // 8. ff2 = ff1 @ W2 + b2 (fp32)
    mma_gemm_kernel<1, false><<<dim3(DM / 128, NT / 128), 256, 65536>>>(
        f1, DFF, w2, DFF, b2, ff2, nullptr, DM, DFF);

    // 9. out = LN(h + ff2)
    add_ln_kernel<false><<<NT, 256>>>(hbuf, ff2, g2, be2, (float*)d_out, nullptr);
}

// round 10
// speedup vs baseline: 2.3894x; 1.0003x over previous
#include <cuda_runtime.h>
#include <cuda_fp16.h>
#include <cstdint>
#include <math.h>

#define DM 512
#define NH 8
#define HD 64
#define DFF 2048
#define BB 2
#define SS 2048
#define NT (BB*SS)
#define BH (BB*NH)
#define QKVLD 1536

#define SWZ(off) ((off) ^ (((off) >> 3) & 0x70))

__device__ __forceinline__ uint32_t smem_to_u32(const void* smem_ptr) {
    uint32_t addr;
    asm("{ .reg .u64 tmp; cvta.to.shared.u64 tmp, %1; cvt.u32.u64 %0, tmp; }"
        : "=r"(addr) : "l"(smem_ptr));
    return addr;
}

#define LDMATRIX_X4(r, addr) \
    asm volatile("ldmatrix.sync.aligned.m8n8.x4.shared.b16 {%0,%1,%2,%3}, [%4];" \
        : "=r"((r)[0]), "=r"((r)[1]), "=r"((r)[2]), "=r"((r)[3]) : "r"(addr))

#define MMA_F16(c, a, b0, b1) \
    asm volatile("mma.sync.aligned.m16n8k16.row.col.f32.f16.f16.f32 " \
        "{%0,%1,%2,%3}, {%4,%5,%6,%7}, {%8,%9}, {%0,%1,%2,%3};" \
        : "+f"((c)[0]), "+f"((c)[1]), "+f"((c)[2]), "+f"((c)[3]) \
        : "r"((a)[0]), "r"((a)[1]), "r"((a)[2]), "r"((a)[3]), "r"(b0), "r"(b1))

#define CP_ASYNC16(dst, src) \
    asm volatile("cp.async.cg.shared.global [%0], [%1], 16;" :: "r"(dst), "l"(src))
#define CP_COMMIT() asm volatile("cp.async.commit_group;" ::: "memory")
#define CP_WAIT(n)  asm volatile("cp.async.wait_group %0;" :: "n"(n) : "memory")

// ===================== static device scratch =====================
__device__ __half g_x[NT * DM];
__device__ __half g_qkv[NT * QKVLD];
__device__ __half g_vt[NT * DM];        // [bh][d][s]
__device__ __half g_ctx[NT * DM];
__device__ __half g_hh[NT * DM];
__device__ __half g_f1[NT * DFF];

__device__ __half g_wqkv[QKVLD * DM];   // [N=1536,K=512]
__device__ __half g_wo[DM * DM];
__device__ __half g_w1[DM * DFF];
__device__ __half g_w2[DM * DFF];
__device__ float g_bqkv[QKVLD];

__device__ float g_ao[2 * NT * DM];     // split-K partials
__device__ float g_h[NT * DM];
__device__ float g_ff2[2 * NT * DM];    // split-K partials

// ===================== helpers =====================
__global__ void cvt_kernel(const float* __restrict__ in, __half* __restrict__ out, int n)
{
    int i = blockIdx.x * 256 + threadIdx.x;
    if (i < n) out[i] = __float2half(in[i]);
}

__global__ void concat_bias_kernel(const float* __restrict__ a, const float* __restrict__ b,
                                   const float* __restrict__ c, float* __restrict__ o)
{
    int i = blockIdx.x * 256 + threadIdx.x;  // 0..1535
    float v = (i < 512) ? a[i] : (i < 1024) ? b[i - 512] : c[i - 1024];
    o[i] = v;
}

// W[K,N] fp32 -> WT[N,K] fp16, one 32x32 tile
__device__ __forceinline__ void wtrans_tile(const float* __restrict__ W, int K, int N,
                                            __half* __restrict__ T, int n0, int k0)
{
    __shared__ float tile[32][33];
    int tx = threadIdx.x & 31, ty = threadIdx.x >> 5;
    #pragma unroll
    for (int i = 0; i < 32; i += 8)
        tile[ty + i][tx] = W[(size_t)(k0 + ty + i) * N + n0 + tx];
    __syncthreads();
    #pragma unroll
    for (int i = 0; i < 32; i += 8)
        T[(size_t)(n0 + ty + i) * K + k0 + tx] = __float2half(tile[tx][ty + i]);
}

// all weight transposes in one launch: QKV [0,768), Wo [768,1024), W1 [1024,2048), W2 [2048,3072)
__global__ void wtransall_kernel(const float* __restrict__ Wq, const float* __restrict__ Wk,
                                 const float* __restrict__ Wv, __half* __restrict__ Wqkv,
                                 const float* __restrict__ Wo, __half* __restrict__ Woh,
                                 const float* __restrict__ W1, __half* __restrict__ W1h,
                                 const float* __restrict__ W2, __half* __restrict__ W2h)
{
    int b = blockIdx.x;
    if (b < 768) {
        int w = b >> 8;              // 0,1,2 -> q,k,v
        int j = b & 255;
        int nt = j & 15, kt = j >> 4;
        const float* W = (w == 0) ? Wq : (w == 1) ? Wk : Wv;
        wtrans_tile(W, DM, DM, Wqkv + (size_t)w * 512 * DM, nt * 32, kt * 32);
    } else if (b < 1024) {
        int j = b - 768;
        int nt = j & 15, kt = j >> 4;
        wtrans_tile(Wo, DM, DM, Woh, nt * 32, kt * 32);
    } else if (b < 2048) {
        int j = b - 1024;            // W1: N=2048 (64 ntiles), K=512 (16 ktiles)
        int nt = j & 63, kt = j >> 6;
        wtrans_tile(W1, DM, DFF, W1h, nt * 32, kt * 32);
    } else {
        int j = b - 2048;            // W2: N=512 (16 ntiles), K=2048 (64 ktiles)
        int nt = j & 15, kt = j >> 4;
        wtrans_tile(W2, DFF, DM, W2h, nt * 32, kt * 32);
    }
}

// v inside qkv buffer [token, 1024 + h*64 + d] -> vT [bh][d][s]
__global__ void vtrans_kernel(const __half* __restrict__ v, __half* __restrict__ ot)
{
    __shared__ unsigned short t[64][65];
    int bh = blockIdx.y; int b = bh >> 3, h = bh & 7;
    int s0 = blockIdx.x * 64;
    for (int i = threadIdx.x; i < 64 * 64; i += 256) {
        int r = i >> 6, c = i & 63;
        t[r][c] = ((const unsigned short*)v)[(size_t)(b * SS + s0 + r) * QKVLD + 1024 + h * 64 + c];
    }
    __syncthreads();
    for (int i = threadIdx.x; i < 64 * 64; i += 256) {
        int d = i >> 6, s = i & 63;
        ((unsigned short*)ot)[((size_t)bh * 64 + d) * SS + s0 + s] = t[s][d];
    }
}

// ===================== fp16 mma.sync GEMM v3 (+ split-K via blockIdx.z) =====================
// BM=128, BN=128, BK=64; 8 warps (4x2), warp tile 32x64; cp.async double-buffered.
// K param = K-extent per z-slice; z-slice kz reads A/B at k offset kz*K, writes Cf + kz*zstride.
// EPI: 0 none (fp32 partial), 1 +bias, 2 +bias+relu
template<int EPI, bool OUT_HALF>
__global__ __launch_bounds__(256, 2) void mma_gemm_kernel(
    const __half* __restrict__ A, long lda,
    const __half* __restrict__ B, long ldb,
    const float* __restrict__ bias,
    float* __restrict__ Cf, __half* __restrict__ Ch, long ldc,
    int K, long zstride)
{
    extern __shared__ __align__(16) char sm[];
    const uint32_t smb = smem_to_u32(sm);

    const int tid = threadIdx.x;
    const int lane = tid & 31;
    const int wid = tid >> 5;
    const int wr = wid >> 1;          // 0..3
    const int wc = wid & 1;           // 0..1
    const int m0 = wr * 32;
    const int n0 = wc * 64;

    const int row0 = blockIdx.y * 128;
    const int col0 = blockIdx.x * 128;
    const long koff = (long)blockIdx.z * K;

    const __half* Ap = A + koff;
    const __half* Bp = B + koff;
    float* Cfp = Cf ? (Cf + (size_t)blockIdx.z * zstride) : nullptr;

    float acc[2][8][4] = {};

    const int aRow = m0 + (lane & 15);
    const int aOff = (lane >> 4) << 4;
    const int bRow = (lane & 7) + ((lane >> 4) & 1) * 8;
    const int bOff = ((lane >> 3) & 1) << 4;

    auto load_chunk = [&](int chunk, int buf) {
        const int c0 = chunk << 6;
        const uint32_t base = smb + buf * 32768;
        #pragma unroll
        for (int t = 0; t < 8; t++) {
            int i = tid + t * 256;        // 0..2047
            int isB = i >> 10;
            int j = i & 1023;
            int r = j >> 3;               // 0..127
            int seg = j & 7;
            const __half* src = isB ? (Bp + (size_t)(col0 + r) * ldb + c0 + seg * 8)
                                    : (Ap + (size_t)(row0 + r) * lda + c0 + seg * 8);
            CP_ASYNC16(base + isB * 16384 + SWZ((uint32_t)(r * 128 + seg * 16)), src);
        }
        CP_COMMIT();
    };

    const int nchunks = K >> 6;
    load_chunk(0, 0);

    for (int chunk = 0; chunk < nchunks; chunk++) {
        const int buf = chunk & 1;
        if (chunk + 1 < nchunks) { load_chunk(chunk + 1, buf ^ 1); CP_WAIT(1); }
        else                      { CP_WAIT(0); }
        __syncthreads();

        const uint32_t abase = smb + buf * 32768;
        const uint32_t bbase = abase + 16384;

        #pragma unroll
        for (int ks = 0; ks < 4; ks++) {
            const int kb = ks * 32;
            uint32_t a[2][4], b[4][4];
            #pragma unroll
            for (int mt = 0; mt < 2; mt++)
                LDMATRIX_X4(a[mt], abase + SWZ((uint32_t)((aRow + mt * 16) * 128 + kb + aOff)));
            #pragma unroll
            for (int np = 0; np < 4; np++)
                LDMATRIX_X4(b[np], bbase + SWZ((uint32_t)((n0 + np * 16 + bRow) * 128 + kb + bOff)));
            #pragma unroll
            for (int mt = 0; mt < 2; mt++)
                #pragma unroll
                for (int nt = 0; nt < 8; nt++) {
                    const int np = nt >> 1, hb = (nt & 1) * 2;
                    MMA_F16(acc[mt][nt], a[mt], b[np][hb], b[np][hb + 1]);
                }
        }
        __syncthreads();
    }

    // ---- epilogue ----
    #pragma unroll
    for (int mt = 0; mt < 2; mt++)
        #pragma unroll
        for (int nt = 0; nt < 8; nt++) {
            const long rbase = row0 + m0 + mt * 16 + (lane >> 2);
            const long col = col0 + n0 + nt * 8 + (lane & 3) * 2;
            float b0f = 0.f, b1f = 0.f;
            if (EPI == 1 || EPI == 2) { b0f = bias[col]; b1f = bias[col + 1]; }
            #pragma unroll
            for (int half = 0; half < 2; half++) {
                const long r = rbase + half * 8;
                float v0 = acc[mt][nt][half * 2 + 0] + b0f;
                float v1 = acc[mt][nt][half * 2 + 1] + b1f;
                if (EPI == 2) { v0 = fmaxf(v0, 0.f); v1 = fmaxf(v1, 0.f); }
                const size_t dst = (size_t)(r * ldc + col);
                if (Cfp) *(float2*)(Cfp + dst) = make_float2(v0, v1);
                if (OUT_HALF) {
                    __half2 hv = __floats2half2_rn(v0, v1);
                    *(__half2*)(Ch + dst) = hv;
                }
            }
        }
}

// ===================== fused flash attention (fp16, single pass) =====================
__global__ __launch_bounds__(256) void flash_attn_kernel(
    const __half* __restrict__ qkv, const __half* __restrict__ vt_,
    __half* __restrict__ ctx_)
{
    __shared__ __align__(16) char sm[32768];
    const uint32_t smb = smem_to_u32(sm);
    const int tid = threadIdx.x, lane = tid & 31, wid = tid >> 5;
    const int bh = blockIdx.y;
    const int b = bh >> 3, h = bh & 7;
    const int q0 = blockIdx.x * 128;

    const __half* qp  = qkv + (size_t)(b * SS + q0) * QKVLD + h * 64;
    const __half* kp  = qkv + (size_t)b * SS * QKVLD + 512 + h * 64;
    const __half* vtp = vt_ + (size_t)bh * 64 * SS;

    // ---- stage Q (128 x 64 fp16 = 16KB), grab fragments ----
    #pragma unroll
    for (int t = 0; t < 4; t++) {
        int i = tid + t * 256;
        int r = i >> 3, seg = i & 7;
        *(float4*)(sm + SWZ((uint32_t)(r * 128 + seg * 16))) =
            *(const float4*)(qp + (size_t)r * QKVLD + seg * 8);
    }
    __syncthreads();
    uint32_t qf[4][4];
    {
        const int aRow = wid * 16 + (lane & 15);
        const int aCol = (lane >> 4) << 4;
        #pragma unroll
        for (int ks = 0; ks < 4; ks++)
            LDMATRIX_X4(qf[ks], smb + SWZ((uint32_t)(aRow * 128 + ks * 32 + aCol)));
    }
    __syncthreads();

    const int bRow = (lane & 7) + ((lane >> 4) & 1) * 8;
    const int bCol = ((lane >> 3) & 1) << 4;

    float acc_o[8][4] = {};
    float m0r = -1e30f, m1r = -1e30f, l0 = 0.f, l1 = 0.f;

    auto load_tile = [&](int it, int buf) {
        const int kv0 = it * 64;
        const uint32_t base = smb + buf * 16384;
        #pragma unroll
        for (int t = 0; t < 4; t++) {
            int i = tid + t * 256;       // 0..1023
            int plane = i >> 9;          // 0 = K, 1 = V
            int r = (i >> 3) & 63;
            int seg = i & 7;
            uint32_t dst = base + plane * 8192 + SWZ((uint32_t)(r * 128 + seg * 16));
            const __half* src = plane ? (vtp + (size_t)r * SS + kv0 + seg * 8)
                                      : (kp + (size_t)(kv0 + r) * QKVLD + seg * 8);
            CP_ASYNC16(dst, src);
        }
        CP_COMMIT();
    };

    load_tile(0, 0);

    const int NIT = SS / 64;
    for (int it = 0; it < NIT; it++) {
        const int buf = it & 1;
        if (it + 1 < NIT) { load_tile(it + 1, buf ^ 1); CP_WAIT(1); }
        else               { CP_WAIT(0); }
        __syncthreads();

        const uint32_t kbase = smb + buf * 16384;
        const uint32_t vbase = kbase + 8192;

        float s[8][4] = {};
        #pragma unroll
        for (int ks = 0; ks < 4; ks++) {
            uint32_t bf[4][4];
            #pragma unroll
            for (int np = 0; np < 4; np++)
                LDMATRIX_X4(bf[np], kbase + SWZ((uint32_t)((np * 16 + bRow) * 128 + ks * 32 + bCol)));
            #pragma unroll
            for (int nt = 0; nt < 8; nt++) {
                const int np = nt >> 1, hb = (nt & 1) * 2;
                MMA_F16(s[nt], qf[ks], bf[np][hb], bf[np][hb + 1]);
            }
        }

        float mx0 = -1e30f, mx1 = -1e30f;
        #pragma unroll
        for (int t = 0; t < 8; t++) {
            mx0 = fmaxf(mx0, fmaxf(s[t][0], s[t][1]));
            mx1 = fmaxf(mx1, fmaxf(s[t][2], s[t][3]));
        }
        mx0 = fmaxf(mx0, __shfl_xor_sync(0xffffffffu, mx0, 1));
        mx0 = fmaxf(mx0, __shfl_xor_sync(0xffffffffu, mx0, 2));
        mx1 = fmaxf(mx1, __shfl_xor_sync(0xffffffffu, mx1, 1));
        mx1 = fmaxf(mx1, __shfl_xor_sync(0xffffffffu, mx1, 2));

        const float mn0 = fmaxf(m0r, 0.125f * mx0);
        const float mn1 = fmaxf(m1r, 0.125f * mx1);
        const float alpha0 = __expf(m0r - mn0);
        const float alpha1 = __expf(m1r - mn1);
        m0r = mn0; m1r = mn1;

        float sum0 = 0.f, sum1 = 0.f;
        #pragma unroll
        for (int t = 0; t < 8; t++) {
            float p0 = __expf(fmaf(0.125f, s[t][0], -mn0));
            float p1 = __expf(fmaf(0.125f, s[t][1], -mn0));
            float p2 = __expf(fmaf(0.125f, s[t][2], -mn1));
            float p3 = __expf(fmaf(0.125f, s[t][3], -mn1));
            sum0 += p0 + p1; sum1 += p2 + p3;
            s[t][0] = p0; s[t][1] = p1; s[t][2] = p2; s[t][3] = p3;
        }
        sum0 += __shfl_xor_sync(0xffffffffu, sum0, 1);
        sum0 += __shfl_xor_sync(0xffffffffu, sum0, 2);
        sum1 += __shfl_xor_sync(0xffffffffu, sum1, 1);
        sum1 += __shfl_xor_sync(0xffffffffu, sum1, 2);
        l0 = l0 * alpha0 + sum0;
        l1 = l1 * alpha1 + sum1;
        #pragma unroll
        for (int t = 0; t < 8; t++) {
            acc_o[t][0] *= alpha0; acc_o[t][1] *= alpha0;
            acc_o[t][2] *= alpha1; acc_o[t][3] *= alpha1;
        }

        #pragma unroll
        for (int j = 0; j < 4; j++) {
            uint32_t pa[4];
            __half2 h0 = __floats2half2_rn(s[2*j][0],   s[2*j][1]);
            __half2 h1 = __floats2half2_rn(s[2*j][2],   s[2*j][3]);
            __half2 h2 = __floats2half2_rn(s[2*j+1][0], s[2*j+1][1]);
            __half2 h3 = __floats2half2_rn(s[2*j+1][2], s[2*j+1][3]);
            pa[0] = *(uint32_t*)&h0; pa[1] = *(uint32_t*)&h1;
            pa[2] = *(uint32_t*)&h2; pa[3] = *(uint32_t*)&h3;

            uint32_t vf[4][4];
            #pragma unroll
            for (int np = 0; np < 4; np++)
                LDMATRIX_X4(vf[np], vbase + SWZ((uint32_t)((np * 16 + bRow) * 128 + j * 32 + bCol)));
            #pragma unroll
            for (int nt = 0; nt < 8; nt++) {
                const int np = nt >> 1, hb = (nt & 1) * 2;
                MMA_F16(acc_o[nt], pa, vf[np][hb], vf[np][hb + 1]);
            }
        }
        __syncthreads();
    }

    const float inv0 = 1.0f / l0;
    const float inv1 = 1.0f / l1;
    const size_t tok0 = (size_t)(b * SS + q0 + wid * 16 + (lane >> 2)) * DM + h * 64;
    #pragma unroll
    for (int t = 0; t < 8; t++) {
        const int dcol = t * 8 + (lane & 3) * 2;
        __half2 o0 = __floats2half2_rn(acc_o[t][0] * inv0, acc_o[t][1] * inv0);
        __half2 o1 = __floats2half2_rn(acc_o[t][2] * inv1, acc_o[t][3] * inv1);
        *(__half2*)(ctx_ + tok0 + dcol) = o0;
        *(__half2*)(ctx_ + tok0 + 8 * DM + dcol) = o1;
    }
}

// ===================== add + LayerNorm (3-input + bias: LN(xa + p0 + p1 + bias)) =====================
template<bool OUT_HALF>
__global__ void add_ln3_kernel(const float* __restrict__ xa,
                               const float* __restrict__ p0, const float* __restrict__ p1,
                               const float* __restrict__ bias,
                               const float* __restrict__ g, const float* __restrict__ be,
                               float* __restrict__ out, __half* __restrict__ oh)
{
    __shared__ float red[256];
    const int row = blockIdx.x;
    const int t = threadIdx.x;
    const size_t base = (size_t)row * DM;

    float v0 = xa[base + t]       + p0[base + t]       + p1[base + t]       + bias[t];
    float v1 = xa[base + t + 256] + p0[base + t + 256] + p1[base + t + 256] + bias[t + 256];

    red[t] = v0 + v1; __syncthreads();
    for (int s = 128; s > 0; s >>= 1) {
        if (t < s) red[t] += red[t + s];
        __syncthreads();
    }
    float mu = red[0] * (1.0f / DM); __syncthreads();

    float d0 = v0 - mu, d1 = v1 - mu;
    red[t] = d0 * d0 + d1 * d1; __syncthreads();
    for (int s = 128; s > 0; s >>= 1) {
        if (t < s) red[t] += red[t + s];
        __syncthreads();
    }
    float r = rsqrtf(red[0] * (1.0f / DM) + 1e-5f);

    float o0 = d0 * r * g[t] + be[t];
    float o1 = d1 * r * g[t + 256] + be[t + 256];
    out[base + t] = o0;
    out[base + t + 256] = o1;
    if (OUT_HALF) {
        oh[base + t] = __float2half(o0);
        oh[base + t + 256] = __float2half(o1);
    }
}

// ===================== launch =====================
extern "C" void kernel_launch(void* const* d_in, const int* in_sizes, int n_in,
                              void* d_out, int out_size)
{
    const float* x   = (const float*)d_in[0];
    const float* Wq  = (const float*)d_in[1];
    const float* bq  = (const float*)d_in[2];
    const float* Wk  = (const float*)d_in[3];
    const float* bk  = (const float*)d_in[4];
    const float* Wv  = (const float*)d_in[5];
    const float* bv  = (const float*)d_in[6];
    const float* Wo  = (const float*)d_in[7];
    const float* bo  = (const float*)d_in[8];
    const float* W1  = (const float*)d_in[9];
    const float* b1  = (const float*)d_in[10];
    const float* W2  = (const float*)d_in[11];
    const float* b2  = (const float*)d_in[12];
    const float* g1  = (const float*)d_in[13];
    const float* be1 = (const float*)d_in[14];
    const float* g2  = (const float*)d_in[15];
    const float* be2 = (const float*)d_in[16];

    #define SYM(p, s) cudaGetSymbolAddress((void**)&p, s)
    float *ao, *hbuf, *ff2, *bqkv;
    __half *xh, *qkv, *vt, *ctx, *hh, *f1;
    __half *wqkv, *wo, *w1, *w2;
    SYM(ao, g_ao); SYM(hbuf, g_h); SYM(ff2, g_ff2); SYM(bqkv, g_bqkv);
    SYM(xh, g_x); SYM(qkv, g_qkv); SYM(vt, g_vt); SYM(ctx, g_ctx);
    SYM(hh, g_hh); SYM(f1, g_f1);
    SYM(wqkv, g_wqkv); SYM(wo, g_wo); SYM(w1, g_w1); SYM(w2, g_w2);
    #undef SYM

    cudaFuncSetAttribute(mma_gemm_kernel<1, true>,
                         cudaFuncAttributeMaxDynamicSharedMemorySize, 65536);
    cudaFuncSetAttribute(mma_gemm_kernel<0, false>,
                         cudaFuncAttributeMaxDynamicSharedMemorySize, 65536);
    cudaFuncSetAttribute(mma_gemm_kernel<2, true>,
                         cudaFuncAttributeMaxDynamicSharedMemorySize, 65536);

    // 1. conversions
    cvt_kernel<<<(NT * DM + 255) / 256, 256>>>(x, xh, NT * DM);
    concat_bias_kernel<<<QKVLD / 256, 256>>>(bq, bk, bv, bqkv);
    wtransall_kernel<<<3072, 256>>>(Wq, Wk, Wv, wqkv, Wo, wo, W1, w1, W2, w2);

    // 2. fused QKV projection: [4096,512] @ [512,1536]
    mma_gemm_kernel<1, true><<<dim3(QKVLD / 128, NT / 128), 256, 65536>>>(
        xh, DM, wqkv, DM, bqkv, nullptr, qkv, QKVLD, DM, 0);

    // 3. transpose V per head
    vtrans_kernel<<<dim3(SS / 64, BH), 256>>>(qkv, vt);

    // 4. fused flash attention -> ctx fp16
    flash_attn_kernel<<<dim3(SS / 128, BH), 256>>>(qkv, vt, ctx);

    // 5. attn partials = ctx @ Wo (split-K=2, fp32 partials; bias folded into LN)
    mma_gemm_kernel<0, false><<<dim3(DM / 128, NT / 128, 2), 256, 65536>>>(
        ctx, DM, wo, DM, nullptr, ao, nullptr, DM, DM / 2, (long)NT * DM);

    // 6. h = LN(x + ao0 + ao1 + bo)
    add_ln3_kernel<true><<<NT, 256>>>(x, ao, ao + (size_t)NT * DM, bo, g1, be1, hbuf, hh);

    // 7. ff1 = relu(h @ W1 + b1)
    mma_gemm_kernel<2, true><<<dim3(DFF / 128, NT / 128), 256, 65536>>>(
        hh, DM, w1, DM, b1, nullptr, f1, DFF, DM, 0);

    // 8. ff2 partials = ff1 @ W2 (split-K=2, fp32 partials; bias folded into LN)
    mma_gemm_kernel<0, false><<<dim3(DM / 128, NT / 128, 2), 256, 65536>>>(
        f1, DFF, w2, DFF, nullptr, ff2, nullptr, DM, DFF / 2, (long)NT * DM);

    // 9. out = LN(h + ff2_0 + ff2_1 + b2)
    add_ln3_kernel<false><<<NT, 256>>>(hbuf, ff2, ff2 + (size_t)NT * DM, b2, g2, be2,
                                       (float*)d_out, nullptr);
}

// round 11
// speedup vs baseline: 2.4342x; 1.0188x over previous
#include <cuda_runtime.h>
#include <cuda_fp16.h>
#include <cstdint>
#include <math.h>

#define DM 512
#define NH 8
#define HD 64
#define DFF 2048
#define BB 2
#define SS 2048
#define NT (BB*SS)
#define BH (BB*NH)
#define QKVLD 1536

#define SWZ(off) ((off) ^ (((off) >> 3) & 0x70))

__device__ __forceinline__ uint32_t smem_to_u32(const void* smem_ptr) {
    uint32_t addr;
    asm("{ .reg .u64 tmp; cvta.to.shared.u64 tmp, %1; cvt.u32.u64 %0, tmp; }"
        : "=r"(addr) : "l"(smem_ptr));
    return addr;
}

#define LDMATRIX_X4(r, addr) \
    asm volatile("ldmatrix.sync.aligned.m8n8.x4.shared.b16 {%0,%1,%2,%3}, [%4];" \
        : "=r"((r)[0]), "=r"((r)[1]), "=r"((r)[2]), "=r"((r)[3]) : "r"(addr))

#define LDMATRIX_X4_TRANS(r, addr) \
    asm volatile("ldmatrix.sync.aligned.m8n8.x4.trans.shared.b16 {%0,%1,%2,%3}, [%4];" \
        : "=r"((r)[0]), "=r"((r)[1]), "=r"((r)[2]), "=r"((r)[3]) : "r"(addr))

#define MMA_F16(c, a, b0, b1) \
    asm volatile("mma.sync.aligned.m16n8k16.row.col.f32.f16.f16.f32 " \
        "{%0,%1,%2,%3}, {%4,%5,%6,%7}, {%8,%9}, {%0,%1,%2,%3};" \
        : "+f"((c)[0]), "+f"((c)[1]), "+f"((c)[2]), "+f"((c)[3]) \
        : "r"((a)[0]), "r"((a)[1]), "r"((a)[2]), "r"((a)[3]), "r"(b0), "r"(b1))

#define CP_ASYNC16(dst, src) \
    asm volatile("cp.async.cg.shared.global [%0], [%1], 16;" :: "r"(dst), "l"(src))
#define CP_COMMIT() asm volatile("cp.async.commit_group;" ::: "memory")
#define CP_WAIT(n)  asm volatile("cp.async.wait_group %0;" :: "n"(n) : "memory")

__device__ __forceinline__ uint32_t h2exp2_(uint32_t x) {
    uint32_t r;
    asm volatile("ex2.approx.f16x2 %0, %1;" : "=r"(r) : "r"(x));
    return r;
}

// ===================== static device scratch =====================
__device__ __half g_x[NT * DM];
__device__ __half g_qkv[NT * QKVLD];
__device__ __half g_ctx[NT * DM];
__device__ __half g_hh[NT * DM];
__device__ __half g_f1[NT * DFF];

__device__ __half g_wqkv[QKVLD * DM];   // [N=1536,K=512]
__device__ __half g_wo[DM * DM];
__device__ __half g_w1[DM * DFF];
__device__ __half g_w2[DM * DFF];
__device__ float g_bqkv[QKVLD];

__device__ float g_ao[2 * NT * DM];     // split-K partials
__device__ float g_h[NT * DM];
__device__ float g_ff2[2 * NT * DM];    // split-K partials

// ===================== helpers =====================
__global__ void cvt_kernel(const float* __restrict__ in, __half* __restrict__ out, int n)
{
    int i = blockIdx.x * 256 + threadIdx.x;
    if (i < n) out[i] = __float2half(in[i]);
}

__global__ void concat_bias_kernel(const float* __restrict__ a, const float* __restrict__ b,
                                   const float* __restrict__ c, float* __restrict__ o)
{
    int i = blockIdx.x * 256 + threadIdx.x;  // 0..1535
    float v = (i < 512) ? a[i] : (i < 1024) ? b[i - 512] : c[i - 1024];
    o[i] = v;
}

// W[K,N] fp32 -> WT[N,K] fp16, one 32x32 tile
__device__ __forceinline__ void wtrans_tile(const float* __restrict__ W, int K, int N,
                                            __half* __restrict__ T, int n0, int k0)
{
    __shared__ float tile[32][33];
    int tx = threadIdx.x & 31, ty = threadIdx.x >> 5;
    #pragma unroll
    for (int i = 0; i < 32; i += 8)
        tile[ty + i][tx] = W[(size_t)(k0 + ty + i) * N + n0 + tx];
    __syncthreads();
    #pragma unroll
    for (int i = 0; i < 32; i += 8)
        T[(size_t)(n0 + ty + i) * K + k0 + tx] = __float2half(tile[tx][ty + i]);
}

// all weight transposes in one launch: QKV [0,768), Wo [768,1024), W1 [1024,2048), W2 [2048,3072)
__global__ void wtransall_kernel(const float* __restrict__ Wq, const float* __restrict__ Wk,
                                 const float* __restrict__ Wv, __half* __restrict__ Wqkv,
                                 const float* __restrict__ Wo, __half* __restrict__ Woh,
                                 const float* __restrict__ W1, __half* __restrict__ W1h,
                                 const float* __restrict__ W2, __half* __restrict__ W2h)
{
    int b = blockIdx.x;
    if (b < 768) {
        int w = b >> 8;              // 0,1,2 -> q,k,v
        int j = b & 255;
        int nt = j & 15, kt = j >> 4;
        const float* W = (w == 0) ? Wq : (w == 1) ? Wk : Wv;
        wtrans_tile(W, DM, DM, Wqkv + (size_t)w * 512 * DM, nt * 32, kt * 32);
    } else if (b < 1024) {
        int j = b - 768;
        int nt = j & 15, kt = j >> 4;
        wtrans_tile(Wo, DM, DM, Woh, nt * 32, kt * 32);
    } else if (b < 2048) {
        int j = b - 1024;            // W1: N=2048 (64 ntiles), K=512 (16 ktiles)
        int nt = j & 63, kt = j >> 6;
        wtrans_tile(W1, DM, DFF, W1h, nt * 32, kt * 32);
    } else {
        int j = b - 2048;            // W2: N=512 (16 ntiles), K=2048 (64 ktiles)
        int nt = j & 15, kt = j >> 4;
        wtrans_tile(W2, DFF, DM, W2h, nt * 32, kt * 32);
    }
}

// ===================== fp16 mma.sync GEMM v3 (+ split-K via blockIdx.z) =====================
// BM=128, BN=128, BK=64; 8 warps (4x2), warp tile 32x64; cp.async double-buffered.
// EPI: 0 none (fp32 partial), 1 +bias, 2 +bias+relu
template<int EPI, bool OUT_HALF>
__global__ __launch_bounds__(256, 2) void mma_gemm_kernel(
    const __half* __restrict__ A, long lda,
    const __half* __restrict__ B, long ldb,
    const float* __restrict__ bias,
    float* __restrict__ Cf, __half* __restrict__ Ch, long ldc,
    int K, long zstride)
{
    extern __shared__ __align__(16) char sm[];
    const uint32_t smb = smem_to_u32(sm);

    const int tid = threadIdx.x;
    const int lane = tid & 31;
    const int wid = tid >> 5;
    const int wr = wid >> 1;
    const int wc = wid & 1;
    const int m0 = wr * 32;
    const int n0 = wc * 64;

    const int row0 = blockIdx.y * 128;
    const int col0 = blockIdx.x * 128;
    const long koff = (long)blockIdx.z * K;

    const __half* Ap = A + koff;
    const __half* Bp = B + koff;
    float* Cfp = Cf ? (Cf + (size_t)blockIdx.z * zstride) : nullptr;

    float acc[2][8][4] = {};

    const int aRow = m0 + (lane & 15);
    const int aOff = (lane >> 4) << 4;
    const int bRow = (lane & 7) + ((lane >> 4) & 1) * 8;
    const int bOff = ((lane >> 3) & 1) << 4;

    auto load_chunk = [&](int chunk, int buf) {
        const int c0 = chunk << 6;
        const uint32_t base = smb + buf * 32768;
        #pragma unroll
        for (int t = 0; t < 8; t++) {
            int i = tid + t * 256;        // 0..2047
            int isB = i >> 10;
            int j = i & 1023;
            int r = j >> 3;
            int seg = j & 7;
            const __half* src = isB ? (Bp + (size_t)(col0 + r) * ldb + c0 + seg * 8)
                                    : (Ap + (size_t)(row0 + r) * lda + c0 + seg * 8);
            CP_ASYNC16(base + isB * 16384 + SWZ((uint32_t)(r * 128 + seg * 16)), src);
        }
        CP_COMMIT();
    };

    const int nchunks = K >> 6;
    load_chunk(0, 0);

    for (int chunk = 0; chunk < nchunks; chunk++) {
        const int buf = chunk & 1;
        if (chunk + 1 < nchunks) { load_chunk(chunk + 1, buf ^ 1); CP_WAIT(1); }
        else                      { CP_WAIT(0); }
        __syncthreads();

        const uint32_t abase = smb + buf * 32768;
        const uint32_t bbase = abase + 16384;

        #pragma unroll
        for (int ks = 0; ks < 4; ks++) {
            const int kb = ks * 32;
            uint32_t a[2][4], b[4][4];
            #pragma unroll
            for (int mt = 0; mt < 2; mt++)
                LDMATRIX_X4(a[mt], abase + SWZ((uint32_t)((aRow + mt * 16) * 128 + kb + aOff)));
            #pragma unroll
            for (int np = 0; np < 4; np++)
                LDMATRIX_X4(b[np], bbase + SWZ((uint32_t)((n0 + np * 16 + bRow) * 128 + kb + bOff)));
            #pragma unroll
            for (int mt = 0; mt < 2; mt++)
                #pragma unroll
                for (int nt = 0; nt < 8; nt++) {
                    const int np = nt >> 1, hb = (nt & 1) * 2;
                    MMA_F16(acc[mt][nt], a[mt], b[np][hb], b[np][hb + 1]);
                }
        }
        __syncthreads();
    }

    #pragma unroll
    for (int mt = 0; mt < 2; mt++)
        #pragma unroll
        for (int nt = 0; nt < 8; nt++) {
            const long rbase = row0 + m0 + mt * 16 + (lane >> 2);
            const long col = col0 + n0 + nt * 8 + (lane & 3) * 2;
            float b0f = 0.f, b1f = 0.f;
            if (EPI == 1 || EPI == 2) { b0f = bias[col]; b1f = bias[col + 1]; }
            #pragma unroll
            for (int half = 0; half < 2; half++) {
                const long r = rbase + half * 8;
                float v0 = acc[mt][nt][half * 2 + 0] + b0f;
                float v1 = acc[mt][nt][half * 2 + 1] + b1f;
                if (EPI == 2) { v0 = fmaxf(v0, 0.f); v1 = fmaxf(v1, 0.f); }
                const size_t dst = (size_t)(r * ldc + col);
                if (Cfp) *(float2*)(Cfp + dst) = make_float2(v0, v1);
                if (OUT_HALF) {
                    __half2 hv = __floats2half2_rn(v0, v1);
                    *(__half2*)(Ch + dst) = hv;
                }
            }
        }
}

// ===================== fused flash attention (fp16, ex2.f16x2 softmax, trans-V) =====================
// grid (SS/128, BH), 256 threads = 8 warps; warp w owns rows [w*16, w*16+16).
// smem 32KB: Q staged at [0,16KB) first; then 2 buffers x (K 8KB + V 8KB).
// V loaded in natural [kv][d] layout; PV B-fragments via ldmatrix.trans.
__global__ __launch_bounds__(256) void flash_attn_kernel(
    const __half* __restrict__ qkv, __half* __restrict__ ctx_)
{
    __shared__ __align__(16) char sm[32768];
    const uint32_t smb = smem_to_u32(sm);
    const int tid = threadIdx.x, lane = tid & 31, wid = tid >> 5;
    const int bh = blockIdx.y;
    const int b = bh >> 3, h = bh & 7;
    const int q0 = blockIdx.x * 128;

    const __half* qp = qkv + (size_t)(b * SS + q0) * QKVLD + h * 64;

    // ---- stage Q (128 x 64 fp16 = 16KB), grab fragments ----
    #pragma unroll
    for (int t = 0; t < 4; t++) {
        int i = tid + t * 256;
        int r = i >> 3, seg = i & 7;
        *(float4*)(sm + SWZ((uint32_t)(r * 128 + seg * 16))) =
            *(const float4*)(qp + (size_t)r * QKVLD + seg * 8);
    }
    __syncthreads();
    uint32_t qf[4][4];
    {
        const int aRow = wid * 16 + (lane & 15);
        const int aCol = (lane >> 4) << 4;
        #pragma unroll
        for (int ks = 0; ks < 4; ks++)
            LDMATRIX_X4(qf[ks], smb + SWZ((uint32_t)(aRow * 128 + ks * 32 + aCol)));
    }
    __syncthreads();

    // K (non-trans B) lane addressing
    const int bRow = (lane & 7) + ((lane >> 4) & 1) * 8;
    const int bCol = ((lane >> 3) & 1) << 4;
    // V (trans B) lane addressing
    const int vRow = (lane & 7) + ((lane >> 3) & 1) * 8;
    const int vCol = (lane >> 4) << 4;

    float acc_o[8][4] = {};
    float m0r = -1e30f, m1r = -1e30f, l0 = 0.f, l1 = 0.f;
    const float C = 0.1803368801f;   // 0.125 * log2(e)

    // tile loader: K plane (rows kv, col base 512) + V plane (rows kv, col base 1024)
    auto load_tile = [&](int it, int buf) {
        const int kv0 = it * 64;
        const uint32_t base = smb + buf * 16384;
        #pragma unroll
        for (int t = 0; t < 4; t++) {
            int i = tid + t * 256;       // 0..1023
            int plane = i >> 9;          // 0 = K, 1 = V
            int r = (i >> 3) & 63;
            int seg = i & 7;
            uint32_t dst = base + plane * 8192 + SWZ((uint32_t)(r * 128 + seg * 16));
            const __half* src = qkv + (size_t)(b * SS + kv0 + r) * QKVLD
                                + 512 + plane * 512 + h * 64 + seg * 8;
            CP_ASYNC16(dst, src);
        }
        CP_COMMIT();
    };

    load_tile(0, 0);

    const int NIT = SS / 64;
    for (int it = 0; it < NIT; it++) {
        const int buf = it & 1;
        if (it + 1 < NIT) { load_tile(it + 1, buf ^ 1); CP_WAIT(1); }
        else               { CP_WAIT(0); }
        __syncthreads();

        const uint32_t kbase = smb + buf * 16384;
        const uint32_t vbase = kbase + 8192;

        // ---- S = Q @ K^T ----
        float s[8][4] = {};
        #pragma unroll
        for (int ks = 0; ks < 4; ks++) {
            uint32_t bf[4][4];
            #pragma unroll
            for (int np = 0; np < 4; np++)
                LDMATRIX_X4(bf[np], kbase + SWZ((uint32_t)((np * 16 + bRow) * 128 + ks * 32 + bCol)));
            #pragma unroll
            for (int nt = 0; nt < 8; nt++) {
                const int np = nt >> 1, hb = (nt & 1) * 2;
                MMA_F16(s[nt], qf[ks], bf[np][hb], bf[np][hb + 1]);
            }
        }

        // ---- online softmax (log2 domain) ----
        float mx0 = -1e30f, mx1 = -1e30f;
        #pragma unroll
        for (int t = 0; t < 8; t++) {
            mx0 = fmaxf(mx0, fmaxf(s[t][0], s[t][1]));
            mx1 = fmaxf(mx1, fmaxf(s[t][2], s[t][3]));
        }
        mx0 = fmaxf(mx0, __shfl_xor_sync(0xffffffffu, mx0, 1));
        mx0 = fmaxf(mx0, __shfl_xor_sync(0xffffffffu, mx0, 2));
        mx1 = fmaxf(mx1, __shfl_xor_sync(0xffffffffu, mx1, 1));
        mx1 = fmaxf(mx1, __shfl_xor_sync(0xffffffffu, mx1, 2));

        const float mn0 = fmaxf(m0r, C * mx0);
        const float mn1 = fmaxf(m1r, C * mx1);
        const float alpha0 = exp2f(m0r - mn0);
        const float alpha1 = exp2f(m1r - mn1);
        m0r = mn0; m1r = mn1;

        // P = 2^(C*s - mn) via ex2.approx.f16x2 -> directly the packed fp16 A-fragments
        uint32_t pa[4][4];
        #pragma unroll
        for (int j = 0; j < 4; j++) {
            __half2 a0 = __floats2half2_rn(fmaf(C, s[2*j][0],   -mn0), fmaf(C, s[2*j][1],   -mn0));
            __half2 a1 = __floats2half2_rn(fmaf(C, s[2*j][2],   -mn1), fmaf(C, s[2*j][3],   -mn1));
            __half2 a2 = __floats2half2_rn(fmaf(C, s[2*j+1][0], -mn0), fmaf(C, s[2*j+1][1], -mn0));
            __half2 a3 = __floats2half2_rn(fmaf(C, s[2*j+1][2], -mn1), fmaf(C, s[2*j+1][3], -mn1));
            pa[j][0] = h2exp2_(*(uint32_t*)&a0);
            pa[j][1] = h2exp2_(*(uint32_t*)&a1);
            pa[j][2] = h2exp2_(*(uint32_t*)&a2);
            pa[j][3] = h2exp2_(*(uint32_t*)&a3);
        }

        // row sums: one fp16 add level (pairs), then fp32 accumulate
        float sum0 = 0.f, sum1 = 0.f;
        #pragma unroll
        for (int j = 0; j < 4; j++) {
            __half2 u0 = __hadd2(*(__half2*)&pa[j][0], *(__half2*)&pa[j][2]);
            __half2 u1 = __hadd2(*(__half2*)&pa[j][1], *(__half2*)&pa[j][3]);
            float2 f0 = __half22float2(u0);
            float2 f1 = __half22float2(u1);
            sum0 += f0.x + f0.y;
            sum1 += f1.x + f1.y;
        }
        sum0 += __shfl_xor_sync(0xffffffffu, sum0, 1);
        sum0 += __shfl_xor_sync(0xffffffffu, sum0, 2);
        sum1 += __shfl_xor_sync(0xffffffffu, sum1, 1);
        sum1 += __shfl_xor_sync(0xffffffffu, sum1, 2);
        l0 = l0 * alpha0 + sum0;
        l1 = l1 * alpha1 + sum1;
        #pragma unroll
        for (int t = 0; t < 8; t++) {
            acc_o[t][0] *= alpha0; acc_o[t][1] *= alpha0;
            acc_o[t][2] *= alpha1; acc_o[t][3] *= alpha1;
        }

        // ---- O += P @ V (V in [kv][d], B-frags via ldmatrix.trans) ----
        #pragma unroll
        for (int j = 0; j < 4; j++) {
            uint32_t vf[4][4];
            #pragma unroll
            for (int np = 0; np < 4; np++)
                LDMATRIX_X4_TRANS(vf[np],
                    vbase + SWZ((uint32_t)((j * 16 + vRow) * 128 + np * 32 + vCol)));
            #pragma unroll
            for (int nt = 0; nt < 8; nt++) {
                const int np = nt >> 1, hb = (nt & 1) * 2;
                MMA_F16(acc_o[nt], pa[j], vf[np][hb], vf[np][hb + 1]);
            }
        }
        __syncthreads();
    }

    const float inv0 = 1.0f / l0;
    const float inv1 = 1.0f / l1;
    const size_t tok0 = (size_t)(b * SS + q0 + wid * 16 + (lane >> 2)) * DM + h * 64;
    #pragma unroll
    for (int t = 0; t < 8; t++) {
        const int dcol = t * 8 + (lane & 3) * 2;
        __half2 o0 = __floats2half2_rn(acc_o[t][0] * inv0, acc_o[t][1] * inv0);
        __half2 o1 = __floats2half2_rn(acc_o[t][2] * inv1, acc_o[t][3] * inv1);
        *(__half2*)(ctx_ + tok0 + dcol) = o0;
        *(__half2*)(ctx_ + tok0 + 8 * DM + dcol) = o1;
    }
}

// ===================== add + LayerNorm (3-input + bias) =====================
template<bool OUT_HALF>
__global__ void add_ln3_kernel(const float* __restrict__ xa,
                               const float* __restrict__ p0, const float* __restrict__ p1,
                               const float* __restrict__ bias,
                               const float* __restrict__ g, const float* __restrict__ be,
                               float* __restrict__ out, __half* __restrict__ oh)
{
    __shared__ float red[256];
    const int row = blockIdx.x;
    const int t = threadIdx.x;
    const size_t base = (size_t)row * DM;

    float v0 = xa[base + t]       + p0[base + t]       + p1[base + t]       + bias[t];
    float v1 = xa[base + t + 256] + p0[base + t + 256] + p1[base + t + 256] + bias[t + 256];

    red[t] = v0 + v1; __syncthreads();
    for (int s = 128; s > 0; s >>= 1) {
        if (t < s) red[t] += red[t + s];
        __syncthreads();
    }
    float mu = red[0] * (1.0f / DM); __syncthreads();

    float d0 = v0 - mu, d1 = v1 - mu;
    red[t] = d0 * d0 + d1 * d1; __syncthreads();
    for (int s = 128; s > 0; s >>= 1) {
        if (t < s) red[t] += red[t + s];
        __syncthreads();
    }
    float r = rsqrtf(red[0] * (1.0f / DM) + 1e-5f);

    float o0 = d0 * r * g[t] + be[t];
    float o1 = d1 * r * g[t + 256] + be[t + 256];
    out[base + t] = o0;
    out[base + t + 256] = o1;
    if (OUT_HALF) {
        oh[base + t] = __float2half(o0);
        oh[base + t + 256] = __float2half(o1);
    }
}

// ===================== launch =====================
extern "C" void kernel_launch(void* const* d_in, const int* in_sizes, int n_in,
                              void* d_out, int out_size)
{
    const float* x   = (const float*)d_in[0];
    const float* Wq  = (const float*)d_in[1];
    const float* bq  = (const float*)d_in[2];
    const float* Wk  = (const float*)d_in[3];
    const float* bk  = (const float*)d_in[4];
    const float* Wv  = (const float*)d_in[5];
    const float* bv  = (const float*)d_in[6];
    const float* Wo  = (const float*)d_in[7];
    const float* bo  = (const float*)d_in[8];
    const float* W1  = (const float*)d_in[9];
    const float* b1  = (const float*)d_in[10];
    const float* W2  = (const float*)d_in[11];
    const float* b2  = (const float*)d_in[12];
    const float* g1  = (const float*)d_in[13];
    const float* be1 = (const float*)d_in[14];
    const float* g2  = (const float*)d_in[15];
    const float* be2 = (const float*)d_in[16];

    #define SYM(p, s) cudaGetSymbolAddress((void**)&p, s)
    float *ao, *hbuf, *ff2, *bqkv;
    __half *xh, *qkv, *ctx, *hh, *f1;
    __half *wqkv, *wo, *w1, *w2;
    SYM(ao, g_ao); SYM(hbuf, g_h); SYM(ff2, g_ff2); SYM(bqkv, g_bqkv);
    SYM(xh, g_x); SYM(qkv, g_qkv); SYM(ctx, g_ctx);
    SYM(hh, g_hh); SYM(f1, g_f1);
    SYM(wqkv, g_wqkv); SYM(wo, g_wo); SYM(w1, g_w1); SYM(w2, g_w2);
    #undef SYM

    cudaFuncSetAttribute(mma_gemm_kernel<1, true>,
                         cudaFuncAttributeMaxDynamicSharedMemorySize, 65536);
    cudaFuncSetAttribute(mma_gemm_kernel<0, false>,
                         cudaFuncAttributeMaxDynamicSharedMemorySize, 65536);
    cudaFuncSetAttribute(mma_gemm_kernel<2, true>,
                         cudaFuncAttributeMaxDynamicSharedMemorySize, 65536);

    // 1. conversions
    cvt_kernel<<<(NT * DM + 255) / 256, 256>>>(x, xh, NT * DM);
    concat_bias_kernel<<<QKVLD / 256, 256>>>(bq, bk, bv, bqkv);
    wtransall_kernel<<<3072, 256>>>(Wq, Wk, Wv, wqkv, Wo, wo, W1, w1, W2, w2);

    // 2. fused QKV projection: [4096,512] @ [512,1536]
    mma_gemm_kernel<1, true><<<dim3(QKVLD / 128, NT / 128), 256, 65536>>>(
        xh, DM, wqkv, DM, bqkv, nullptr, qkv, QKVLD, DM, 0);

    // 3. fused flash attention (V read directly from qkv) -> ctx fp16
    flash_attn_kernel<<<dim3(SS / 128, BH), 256>>>(qkv, ctx);

    // 4. attn partials = ctx @ Wo (split-K=2, fp32 partials; bias folded into LN)
    mma_gemm_kernel<0, false><<<dim3(DM / 128, NT / 128, 2), 256, 65536>>>(
        ctx, DM, wo, DM, nullptr, ao, nullptr, DM, DM / 2, (long)NT * DM);

    // 5. h = LN(x + ao0 + ao1 + bo)
    add_ln3_kernel<true><<<NT, 256>>>(x, ao, ao + (size_t)NT * DM, bo, g1, be1, hbuf, hh);

    // 6. ff1 = relu(h @ W1 + b1)
    mma_gemm_kernel<2, true><<<dim3(DFF / 128, NT / 128), 256, 65536>>>(
        hh, DM, w1, DM, b1, nullptr, f1, DFF, DM, 0);

    // 7. ff2 partials = ff1 @ W2 (split-K=2, fp32 partials; bias folded into LN)
    mma_gemm_kernel<0, false><<<dim3(DM / 128, NT / 128, 2), 256, 65536>>>(
        f1, DFF, w2, DFF, nullptr, ff2, nullptr, DM, DFF / 2, (long)NT * DM);

    // 8. out = LN(h + ff2_0 + ff2_1 + b2)
    add_ln3_kernel<false><<<NT, 256>>>(hbuf, ff2, ff2 + (size_t)NT * DM, b2, g2, be2,
                                       (float*)d_out, nullptr);
}